// round 1
// baseline (speedup 1.0000x reference)
#include <cuda_runtime.h>
#include <cstdint>

#define NN 100000
#define NE 600000
#define NR 3
#define NL 3
#define DIM 128
#define BN_EPS 1e-5f

// ---------------- scratch (static device allocations only) ----------------
__device__ float g_h[(size_t)NN * DIM];     // layer output
__device__ float g_m[(size_t)NN * DIM];     // per-relation aggregation / fc output
__device__ float g_agg[(size_t)NN * DIM];   // summed conv output
__device__ float g_deg[6 * NN];             // [0..3): rsqrt(deg_out) per rel, [3..6): rsqrt(deg_in)
__device__ float g_stats[2 * DIM];          // column sum, sumsq

// ---------------- utility ----------------
__global__ void __launch_bounds__(256) k_zero(float4* p, int n4) {
    int i = blockIdx.x * 256 + threadIdx.x;
    if (i < n4) p[i] = make_float4(0.f, 0.f, 0.f, 0.f);
}

// ---------------- degrees ----------------
__global__ void __launch_bounds__(256) k_deg(const int* __restrict__ edges, float* __restrict__ deg) {
    int i = blockIdx.x * 256 + threadIdx.x;
    if (i >= NR * NE) return;
    int r = i / NE;
    int e = i - r * NE;
    int s = edges[(size_t)(r * 2 + 0) * NE + e];
    int d = edges[(size_t)(r * 2 + 1) * NE + e];
    atomicAdd(&deg[r * NN + s], 1.f);
    atomicAdd(&deg[(NR + r) * NN + d], 1.f);
}

__global__ void __launch_bounds__(256) k_degfin(float* __restrict__ deg) {
    int i = blockIdx.x * 256 + threadIdx.x;
    if (i < 6 * NN) deg[i] = rsqrtf(fmaxf(deg[i], 1.f));
}

// ---------------- scatter-add: m[dst] += h[src] * dinv_out[src] ----------------
// one warp per edge; lane handles 4 consecutive floats; vectorized L2 reduction
__global__ void __launch_bounds__(256) k_scatter(const float* __restrict__ h,
                                                 const int* __restrict__ src,
                                                 const int* __restrict__ dst,
                                                 const float* __restrict__ dinv,
                                                 float* __restrict__ m) {
    int gw = (blockIdx.x * 256 + threadIdx.x) >> 5;
    int lane = threadIdx.x & 31;
    if (gw >= NE) return;
    int s = __ldg(&src[gw]);
    int d = __ldg(&dst[gw]);
    float sc = __ldg(&dinv[s]);
    float4 v = *(const float4*)(h + (size_t)s * DIM + lane * 4);
    v.x *= sc; v.y *= sc; v.z *= sc; v.w *= sc;
    float* p = m + (size_t)d * DIM + lane * 4;
    asm volatile("red.global.add.v4.f32 [%0], {%1, %2, %3, %4};"
                 :: "l"(p), "f"(v.x), "f"(v.y), "f"(v.z), "f"(v.w)
                 : "memory");
}

// ---------------- SGEMM: C[M,128] (+)= (rowscale .* A) @ W[128,128] + bias ----------------
// 64x128 block tile, BK=16, 256 threads, 8x4 per-thread tile.
template <bool ACCUM, bool RELU>
__global__ void __launch_bounds__(256) k_gemm(const float* __restrict__ A,
                                              const float* __restrict__ W,
                                              const float* __restrict__ bias,
                                              const float* __restrict__ rowscale,
                                              float* __restrict__ C, int M) {
    __shared__ float As[16][72];   // padded: conflict-free transposed stores
    __shared__ float Bs[16][128];

    int tid = threadIdx.x;
    int row0 = blockIdx.x * 64;
    int rbase = (tid >> 5) * 8;     // warp -> 8 rows (broadcast A frags within warp)
    int cbase = (tid & 31) * 4;     // lane -> 4 cols

    // A-load mapping: thread loads one float4 per k-tile
    int arow = tid >> 2;            // 0..63
    int ak = (tid & 3) * 4;         // 0,4,8,12
    int grow = row0 + arow;
    bool rowok = grow < M;
    float rs = 1.f;
    if (rowok && rowscale) rs = rowscale[grow];
    const float4* Ar = (const float4*)(A + (size_t)grow * DIM);

    // B-load mapping: thread loads two float4 per k-tile
    int bk1 = tid >> 5;             // 0..7
    int bn1 = (tid & 31) * 4;

    float acc[8][4];
#pragma unroll
    for (int i = 0; i < 8; i++)
#pragma unroll
        for (int j = 0; j < 4; j++) acc[i][j] = 0.f;

    for (int kt = 0; kt < 8; ++kt) {
        float4 av = rowok ? Ar[kt * 4 + (tid & 3)] : make_float4(0.f, 0.f, 0.f, 0.f);
        As[ak + 0][arow] = av.x * rs;
        As[ak + 1][arow] = av.y * rs;
        As[ak + 2][arow] = av.z * rs;
        As[ak + 3][arow] = av.w * rs;
        *(float4*)&Bs[bk1][bn1]     = *(const float4*)(W + (size_t)(kt * 16 + bk1) * DIM + bn1);
        *(float4*)&Bs[bk1 + 8][bn1] = *(const float4*)(W + (size_t)(kt * 16 + bk1 + 8) * DIM + bn1);
        __syncthreads();
#pragma unroll
        for (int kk = 0; kk < 16; ++kk) {
            float4 b4 = *(float4*)&Bs[kk][cbase];
            float4 a0 = *(float4*)&As[kk][rbase];
            float4 a1 = *(float4*)&As[kk][rbase + 4];
            float a[8] = {a0.x, a0.y, a0.z, a0.w, a1.x, a1.y, a1.z, a1.w};
#pragma unroll
            for (int i = 0; i < 8; i++) {
                acc[i][0] += a[i] * b4.x;
                acc[i][1] += a[i] * b4.y;
                acc[i][2] += a[i] * b4.z;
                acc[i][3] += a[i] * b4.w;
            }
        }
        __syncthreads();
    }

    float4 bv = *(const float4*)(bias + cbase);
#pragma unroll
    for (int i = 0; i < 8; i++) {
        int r = row0 + rbase + i;
        if (r < M) {
            float4 c;
            c.x = acc[i][0] + bv.x;
            c.y = acc[i][1] + bv.y;
            c.z = acc[i][2] + bv.z;
            c.w = acc[i][3] + bv.w;
            float* cp = C + (size_t)r * DIM + cbase;
            if (ACCUM) {
                float4 o = *(float4*)cp;
                c.x += o.x; c.y += o.y; c.z += o.z; c.w += o.w;
            }
            if (RELU) {
                c.x = fmaxf(c.x, 0.f); c.y = fmaxf(c.y, 0.f);
                c.z = fmaxf(c.z, 0.f); c.w = fmaxf(c.w, 0.f);
            }
            *(float4*)cp = c;
        }
    }
}

// ---------------- BatchNorm ----------------
__global__ void __launch_bounds__(128) k_bnstats(const float* __restrict__ h,
                                                 float* __restrict__ stats) {
    int c = threadIdx.x;
    float s = 0.f, s2 = 0.f;
    for (int r = blockIdx.x; r < NN; r += gridDim.x) {
        float v = h[(size_t)r * DIM + c];
        s += v;
        s2 += v * v;
    }
    atomicAdd(&stats[c], s);
    atomicAdd(&stats[DIM + c], s2);
}

__global__ void __launch_bounds__(256) k_bnnorm(const float* __restrict__ h,
                                                const float* __restrict__ stats,
                                                const float* __restrict__ gamma,
                                                const float* __restrict__ beta,
                                                float* __restrict__ out) {
    int i = blockIdx.x * 256 + threadIdx.x;    // float4 index
    if (i >= NN * DIM / 4) return;
    int c = (i & 31) * 4;                       // 32 float4 per row
    float4 v = *(const float4*)(h + (size_t)i * 4);
    float o[4];
    float vin[4] = {v.x, v.y, v.z, v.w};
#pragma unroll
    for (int j = 0; j < 4; j++) {
        float mean = stats[c + j] * (1.f / NN);
        float var = stats[DIM + c + j] * (1.f / NN) - mean * mean;
        float inv = rsqrtf(var + BN_EPS);
        o[j] = (vin[j] - mean) * inv * gamma[c + j] + beta[c + j];
    }
    float4 ov = make_float4(o[0], o[1], o[2], o[3]);
    *(float4*)(out + (size_t)i * 4) = ov;
}

// ---------------- launch ----------------
extern "C" void kernel_launch(void* const* d_in, const int* in_sizes, int n_in,
                              void* d_out, int out_size) {
    const float* x      = (const float*)d_in[0];
    const int*   edges  = (const int*)d_in[1];    // [3][2][NE]
    const float* conv_W = (const float*)d_in[2];  // [3][3][128][128]
    const float* conv_b = (const float*)d_in[3];  // [3][3][128]
    const float* fc_W   = (const float*)d_in[4];  // [3][128][128]
    const float* fc_b   = (const float*)d_in[5];  // [3][128]
    const float* gamma  = (const float*)d_in[6];  // [3][128]
    const float* beta   = (const float*)d_in[7];  // [3][128]
    float* out = (float*)d_out;

    float *h, *m, *agg, *deg, *stats;
    cudaGetSymbolAddress((void**)&h, g_h);
    cudaGetSymbolAddress((void**)&m, g_m);
    cudaGetSymbolAddress((void**)&agg, g_agg);
    cudaGetSymbolAddress((void**)&deg, g_deg);
    cudaGetSymbolAddress((void**)&stats, g_stats);

    const int nh4 = NN * DIM / 4;

    // degrees (same for all layers)
    k_zero<<<(6 * NN / 4 + 255) / 256, 256>>>((float4*)deg, 6 * NN / 4);
    k_deg<<<(NR * NE + 255) / 256, 256>>>(edges, deg);
    k_degfin<<<(6 * NN + 255) / 256, 256>>>(deg);

    for (int l = 0; l < NL; ++l) {
        const float* hin = (l == 0) ? x : h;
        k_zero<<<(nh4 + 255) / 256, 256>>>((float4*)agg, nh4);
        for (int r = 0; r < NR; ++r) {
            k_zero<<<(nh4 + 255) / 256, 256>>>((float4*)m, nh4);
            k_scatter<<<(NE * 32 + 255) / 256, 256>>>(
                hin,
                edges + (size_t)(r * 2 + 0) * NE,
                edges + (size_t)(r * 2 + 1) * NE,
                deg + r * NN, m);
            k_gemm<true, false><<<(NN + 63) / 64, 256>>>(
                m,
                conv_W + ((size_t)l * NR + r) * DIM * DIM,
                conv_b + ((size_t)l * NR + r) * DIM,
                deg + (NR + r) * NN,
                agg, NN);
        }
        // FC + ReLU
        k_gemm<false, true><<<(NN + 63) / 64, 256>>>(
            agg, fc_W + (size_t)l * DIM * DIM, fc_b + (size_t)l * DIM,
            nullptr, m, NN);
        // BatchNorm (training-mode batch stats)
        k_zero<<<1, 256>>>((float4*)stats, 2 * DIM / 4);
        k_bnstats<<<2048, 128>>>(m, stats);
        k_bnnorm<<<(nh4 + 255) / 256, 256>>>(m, stats,
                                             gamma + (size_t)l * DIM,
                                             beta + (size_t)l * DIM,
                                             (l == NL - 1) ? out : h);
    }
}

// round 4
// speedup vs baseline: 1.0604x; 1.0604x over previous
#include <cuda_runtime.h>
#include <cuda_bf16.h>
#include <cstdint>

#define NN 100000
#define NE 600000
#define NR 3
#define NL 3
#define DIM 128
#define BN_EPS 1e-5f
#define MTILES ((NN + 127) / 128)

// Feature detection: tcgen05 needs arch-SPECIFIC (sm_103a / sm_100a) or family target.
#if defined(__CUDA_ARCH_FEAT_SM103_ALL) || defined(__CUDA_ARCH_FEAT_SM100_ALL) || \
    defined(__CUDA_ARCH_FEAT_SM101_ALL) || \
    (defined(__CUDA_ARCH_FAMILY_SPECIFIC__) && (__CUDA_ARCH_FAMILY_SPECIFIC__ >= 1000)) || \
    (defined(__CUDA_ARCH_SPECIFIC__) && (__CUDA_ARCH_SPECIFIC__ >= 1000))
#define HAS_TCGEN05 1
#else
#define HAS_TCGEN05 0
#endif

// ---------------- scratch (static device allocations only) ----------------
__device__ __align__(16) float g_h[(size_t)NN * DIM];
__device__ __align__(16) float g_m[(size_t)NN * DIM];
__device__ __align__(16) float g_agg[(size_t)NN * DIM];
__device__ __align__(16) float g_deg[6 * NN];
__device__ __align__(16) float g_stats[2 * DIM];
__device__ __align__(16) uint8_t g_Wbf[12 * 65536];   // per matrix: 32KB hi + 32KB lo bf16 image (smem-ready, swizzled)
__device__ __align__(16) float g_fceff[NL * DIM];

// ---------------- PTX helpers ----------------
__device__ __forceinline__ uint32_t smem_u32(const void* p) {
    uint32_t a;
    asm("{ .reg .u64 t; cvta.to.shared.u64 t, %1; cvt.u32.u64 %0, t; }" : "=r"(a) : "l"(p));
    return a;
}

#if HAS_TCGEN05
__device__ __forceinline__ uint32_t elect_one() {
    uint32_t pred;
    asm volatile("{\n\t.reg .pred p;\n\telect.sync _|p, 0xFFFFFFFF;\n\tselp.b32 %0, 1, 0, p;\n\t}" : "=r"(pred));
    return pred;
}
#define MBARRIER_INIT(addr, cnt) \
    asm volatile("mbarrier.init.shared.b64 [%0], %1;" :: "r"((uint32_t)(addr)), "r"((uint32_t)(cnt)) : "memory")
__device__ __forceinline__ void mbar_wait(uint32_t mbar, uint32_t parity) {
    asm volatile(
        "{\n\t.reg .pred P;\n\t"
        "WL_%=:\n\t"
        "mbarrier.try_wait.parity.acquire.cta.shared::cta.b64 P, [%0], %1, 0x989680;\n\t"
        "@P bra.uni WD_%=;\n\t"
        "bra.uni WL_%=;\n\t"
        "WD_%=:\n\t}"
        :: "r"(mbar), "r"(parity) : "memory");
}
#define TCGEN05_ALLOC(smem_addr, n) \
    asm volatile("tcgen05.alloc.cta_group::1.sync.aligned.shared::cta.b32 [%0], %1;" \
                 :: "r"((uint32_t)(smem_addr)), "r"((uint32_t)(n)) : "memory")
#define TCGEN05_DEALLOC(tmem, n) \
    asm volatile("tcgen05.dealloc.cta_group::1.sync.aligned.b32 %0, %1;" :: "r"(tmem), "r"((uint32_t)(n)))
#define TCGEN05_COMMIT(mbar) \
    asm volatile("tcgen05.commit.cta_group::1.mbarrier::arrive::one.shared::cluster.b64 [%0];" \
                 :: "r"((uint32_t)(mbar)) : "memory")
#define TCGEN05_WAIT_LD() asm volatile("tcgen05.wait::ld.sync.aligned;" ::: "memory")
#define TCGEN05_FENCE_AFTER() asm volatile("tcgen05.fence::after_thread_sync;" ::: "memory")
#define FENCE_ASYNC_SHARED() asm volatile("fence.proxy.async.shared::cta;" ::: "memory")

#define TCGEN05_LD_32X32B_X32(r, tmem_addr) \
    asm volatile( \
        "tcgen05.ld.sync.aligned.32x32b.x32.b32 " \
        "{%0, %1, %2, %3, %4, %5, %6, %7, " \
        " %8, %9, %10, %11, %12, %13, %14, %15, " \
        " %16, %17, %18, %19, %20, %21, %22, %23, " \
        " %24, %25, %26, %27, %28, %29, %30, %31}, [%32];" \
        : "=r"((r)[0]),  "=r"((r)[1]),  "=r"((r)[2]),  "=r"((r)[3]), \
          "=r"((r)[4]),  "=r"((r)[5]),  "=r"((r)[6]),  "=r"((r)[7]), \
          "=r"((r)[8]),  "=r"((r)[9]),  "=r"((r)[10]), "=r"((r)[11]), \
          "=r"((r)[12]), "=r"((r)[13]), "=r"((r)[14]), "=r"((r)[15]), \
          "=r"((r)[16]), "=r"((r)[17]), "=r"((r)[18]), "=r"((r)[19]), \
          "=r"((r)[20]), "=r"((r)[21]), "=r"((r)[22]), "=r"((r)[23]), \
          "=r"((r)[24]), "=r"((r)[25]), "=r"((r)[26]), "=r"((r)[27]), \
          "=r"((r)[28]), "=r"((r)[29]), "=r"((r)[30]), "=r"((r)[31]) \
        : "r"(tmem_addr))

static constexpr uint64_t SMEM_DESC_BASE_SW128 =
    (uint64_t(2) << 61) | (uint64_t(1) << 46) | (uint64_t(64) << 32) | (uint64_t(1) << 16);
#define MAKE_SMEM_DESC(base_addr) (SMEM_DESC_BASE_SW128 | ((uint64_t)((base_addr) >> 4) & 0x3FFF))

__device__ __forceinline__ void mma_f16_ss(uint32_t d, uint64_t a, uint64_t b, uint32_t idesc, int acc) {
    asm volatile(
        "{\n\t.reg .pred p;\n\tsetp.ne.u32 p, %4, 0;\n\t"
        "tcgen05.mma.cta_group::1.kind::f16 [%0], %1, %2, %3, {%5, %5, %5, %5}, p;\n\t}"
        :: "r"(d), "l"(a), "l"(b), "r"(idesc), "r"(acc), "r"(0u) : "memory");
}
// idesc: dtype=F32(1<<4) atype=BF16(1<<7) btype=BF16(1<<10) N/8<<17 M/16<<24 (M=128,N=128)
#define MMA_IDESC 0x8200490u
#endif  // HAS_TCGEN05

// Blocked SW128 atom layout for a 128x128 bf16 tile:
// atom = 8 rows x 64 cols (1024B); atom_offset = atom_row + atom_col*16 (16 atom-rows).
__host__ __device__ __forceinline__ uint32_t tile_off(int row, int col) {
    uint32_t off = (uint32_t)(((row >> 3) + ((col >> 6) << 4)) << 10) | ((row & 7) << 7) | ((col & 63) << 1);
    return off ^ ((off >> 3) & 0x70);
}

// ---------------- utility ----------------
__global__ void __launch_bounds__(256) k_zero(float4* p, int n4) {
    int i = blockIdx.x * 256 + threadIdx.x;
    if (i < n4) p[i] = make_float4(0.f, 0.f, 0.f, 0.f);
}

// ---------------- degrees ----------------
__global__ void __launch_bounds__(256) k_deg(const int* __restrict__ edges, float* __restrict__ deg) {
    int i = blockIdx.x * 256 + threadIdx.x;
    if (i >= NR * NE) return;
    int r = i / NE;
    int e = i - r * NE;
    int s = edges[(size_t)(r * 2 + 0) * NE + e];
    int d = edges[(size_t)(r * 2 + 1) * NE + e];
    atomicAdd(&deg[r * NN + s], 1.f);
    atomicAdd(&deg[(NR + r) * NN + d], 1.f);
}
__global__ void __launch_bounds__(256) k_degfin(float* __restrict__ deg) {
    int i = blockIdx.x * 256 + threadIdx.x;
    if (i < 6 * NN) deg[i] = rsqrtf(fmaxf(deg[i], 1.f));
}

// ---------------- weight prep: fp32 -> (bf16 hi, bf16 lo) swizzled image ----------------
__global__ void __launch_bounds__(256) k_wprep(const float* __restrict__ convW,
                                               const float* __restrict__ fcW,
                                               uint8_t* __restrict__ wbf) {
    int idx = blockIdx.x * 256 + threadIdx.x;
    if (idx >= 12 * 16384) return;
    int w = idx >> 14;
    int e = idx & 16383;           // e = k*128 + n
    int k = e >> 7, n = e & 127;
    const float* W = (w < 9) ? (convW + (size_t)w * 16384) : (fcW + (size_t)(w - 9) * 16384);
    float v = W[e];
    __nv_bfloat16 hi = __float2bfloat16(v);
    __nv_bfloat16 lo = __float2bfloat16(v - __bfloat162float(hi));
    uint32_t off = tile_off(n, k);  // B = W^T stored K-major: row=n, col=k
    *(__nv_bfloat16*)(wbf + (size_t)w * 65536 + off) = hi;
    *(__nv_bfloat16*)(wbf + (size_t)w * 65536 + 32768 + off) = lo;
}

// fceff_b[l] = fc_b[l] + (sum_r conv_b[l,r]) @ fc_W[l]
__global__ void __launch_bounds__(128) k_bprep(const float* __restrict__ conv_b,
                                               const float* __restrict__ fc_W,
                                               const float* __restrict__ fc_b,
                                               float* __restrict__ fceff) {
    __shared__ float bs[DIM];
    int l = blockIdx.x, n = threadIdx.x;
    bs[n] = conv_b[(size_t)(l * 3 + 0) * DIM + n] + conv_b[(size_t)(l * 3 + 1) * DIM + n] +
            conv_b[(size_t)(l * 3 + 2) * DIM + n];
    __syncthreads();
    float acc = fc_b[(size_t)l * DIM + n];
    for (int k = 0; k < DIM; k++) acc += bs[k] * fc_W[(size_t)l * DIM * DIM + (size_t)k * DIM + n];
    fceff[(size_t)l * DIM + n] = acc;
}

// ---------------- scatter-add: agg[dst] += m[src] * dinv_out[src] * dinv_in[dst] ----------------
__global__ void __launch_bounds__(256) k_scatter(const float* __restrict__ m,
                                                 const int* __restrict__ src,
                                                 const int* __restrict__ dst,
                                                 const float* __restrict__ dinv_o,
                                                 const float* __restrict__ dinv_i,
                                                 float* __restrict__ agg) {
    int gw = (blockIdx.x * 256 + threadIdx.x) >> 5;
    int lane = threadIdx.x & 31;
    if (gw >= NE) return;
    int s = __ldg(&src[gw]);
    int d = __ldg(&dst[gw]);
    float sc = __ldg(&dinv_o[s]) * __ldg(&dinv_i[d]);
    float4 v = *(const float4*)(m + (size_t)s * DIM + lane * 4);
    v.x *= sc; v.y *= sc; v.z *= sc; v.w *= sc;
    float* p = agg + (size_t)d * DIM + lane * 4;
    asm volatile("red.global.add.v4.f32 [%0], {%1, %2, %3, %4};"
                 :: "l"(p), "f"(v.x), "f"(v.y), "f"(v.z), "f"(v.w) : "memory");
}

// ---------------- GEMM: C[M,128] = A[M,128] @ W[128,128] (+bias)(+relu) ----------------
// tcgen05 path: bf16 hi/lo split, 3 SS-MMA passes, fp32 TMEM accum.
// fallback path (non-'a' target): scalar FFMA, W reconstructed (hi+lo) from the image.
#define SM_TMEM 0
#define SM_MBAR 8
#define SM_AHI 1024
#define SM_ALO (SM_AHI + 32768)
#define SM_B   (SM_ALO + 32768)
#define SM_TOTAL (SM_B + 65536)

template <bool RELU>
__global__ void __launch_bounds__(256, 1) k_gemm_tc(const float4* __restrict__ A,
                                                    const uint8_t* __restrict__ Wimg,
                                                    const float* __restrict__ bias,
                                                    float* __restrict__ C, int M) {
    extern __shared__ char sm[];
    int tid = threadIdx.x, wid = tid >> 5, lid = tid & 31;
    int row0 = blockIdx.x * 128;

#if HAS_TCGEN05
    uint32_t smb = smem_u32(sm);
    // Warp 0 allocates TMEM; other warps do NOTHING (no relinquish: it is illegal
    // for an alloc to execute after ANY thread of the CTA relinquishes — racy before).
    if (tid == 0) MBARRIER_INIT(smb + SM_MBAR, 1);
    if (wid == 0) { TCGEN05_ALLOC(smb + SM_TMEM, 128); }
    __syncthreads();   // alloc + mbar init settled for all warps

    // copy weight hi+lo images (pre-swizzled) into smem
    {
        const float4* Wv = (const float4*)Wimg;
        float4* Bv = (float4*)(sm + SM_B);
#pragma unroll
        for (int i = 0; i < 16; i++) Bv[tid + i * 256] = Wv[tid + i * 256];
    }

    // load A tile fp32, split into bf16 hi/lo, store swizzled
    for (int i = tid; i < 4096; i += 256) {
        int row = i >> 5;
        int c4 = i & 31;
        int grow = row0 + row;
        float4 v = make_float4(0.f, 0.f, 0.f, 0.f);
        if (grow < M) v = A[(size_t)grow * 32 + c4];
        __nv_bfloat162 h01 = __floats2bfloat162_rn(v.x, v.y);
        __nv_bfloat162 h23 = __floats2bfloat162_rn(v.z, v.w);
        float lx = v.x - __bfloat162float(h01.x);
        float ly = v.y - __bfloat162float(h01.y);
        float lz = v.z - __bfloat162float(h23.x);
        float lw = v.w - __bfloat162float(h23.y);
        __nv_bfloat162 l01 = __floats2bfloat162_rn(lx, ly);
        __nv_bfloat162 l23 = __floats2bfloat162_rn(lz, lw);
        uint32_t off = tile_off(row, c4 * 4);
        uint2 hv, lv;
        hv.x = *(uint32_t*)&h01; hv.y = *(uint32_t*)&h23;
        lv.x = *(uint32_t*)&l01; lv.y = *(uint32_t*)&l23;
        *(uint2*)(sm + SM_AHI + off) = hv;
        *(uint2*)(sm + SM_ALO + off) = lv;
    }

    FENCE_ASYNC_SHARED();
    __syncthreads();

    uint32_t tmem;
    asm volatile("ld.shared.b32 %0, [%1];" : "=r"(tmem) : "r"(smb + SM_TMEM));

    if (wid == 0 && elect_one()) {
        uint64_t aH = MAKE_SMEM_DESC(smb + SM_AHI);
        uint64_t aL = MAKE_SMEM_DESC(smb + SM_ALO);
        uint64_t bH = MAKE_SMEM_DESC(smb + SM_B);
        uint64_t bL = MAKE_SMEM_DESC(smb + SM_B + 32768);
        uint64_t ad[3] = {aH, aH, aL};
        uint64_t bd[3] = {bH, bL, bH};
#pragma unroll
        for (int p = 0; p < 3; p++) {
#pragma unroll
            for (int s = 0; s < 8; s++) {
                // k-step 16 bf16 = 32B = 2 desc units; atom-col 1 base = 16KB = 1024 units
                uint64_t o = (s < 4) ? (uint64_t)(s * 2) : (uint64_t)(1024 + (s - 4) * 2);
                mma_f16_ss(tmem, ad[p] + o, bd[p] + o, MMA_IDESC, !(p == 0 && s == 0));
            }
        }
        TCGEN05_COMMIT(smb + SM_MBAR);
    }

    mbar_wait(smb + SM_MBAR, 0);
    TCGEN05_FENCE_AFTER();

    // epilogue: rows by subpartition (wid&3), col halves by (wid>>2)
    int rb = (wid & 3) * 32 + lid;
    int grow = row0 + rb;
    int chalf = (wid >> 2) * 64;
#pragma unroll
    for (int h = 0; h < 2; h++) {
        int cb = chalf + h * 32;
        uint32_t dr[32];
        TCGEN05_LD_32X32B_X32(dr, tmem + cb);
        TCGEN05_WAIT_LD();
        if (grow < M) {
            float* op = C + (size_t)grow * DIM + cb;
#pragma unroll
            for (int j = 0; j < 8; j++) {
                float4 c;
                c.x = __uint_as_float(dr[4 * j + 0]);
                c.y = __uint_as_float(dr[4 * j + 1]);
                c.z = __uint_as_float(dr[4 * j + 2]);
                c.w = __uint_as_float(dr[4 * j + 3]);
                if (bias) {
                    float4 bv = *(const float4*)(bias + cb + 4 * j);
                    c.x += bv.x; c.y += bv.y; c.z += bv.z; c.w += bv.w;
                }
                if (RELU) {
                    c.x = fmaxf(c.x, 0.f); c.y = fmaxf(c.y, 0.f);
                    c.z = fmaxf(c.z, 0.f); c.w = fmaxf(c.w, 0.f);
                }
                *(float4*)(op + 4 * j) = c;
            }
        }
    }

    __syncthreads();
    if (wid == 0) TCGEN05_DEALLOC(tmem, 128);

#else  // ---------------- fallback: scalar FFMA GEMM (non-'a' target) ----------------
    float* Wf = (float*)sm;                 // [128][128] fp32, 64KB
    float* As = Wf + 16384;                 // [16][72] padded, staged per k-tile

    // reconstruct fp32 W from hi+lo swizzled image
    for (int i = tid; i < 16384; i += 256) {
        int k = i >> 7, n = i & 127;
        uint32_t off = tile_off(n, k);
        float hi = __bfloat162float(*(const __nv_bfloat16*)(Wimg + off));
        float lo = __bfloat162float(*(const __nv_bfloat16*)(Wimg + 32768 + off));
        Wf[i] = hi + lo;
    }
    __syncthreads();

    int rbase = (tid >> 5) * 8;
    int cbase = (tid & 31) * 4;
    int arow = tid >> 2;
    int ak = (tid & 3) * 4;

    for (int half = 0; half < 2; half++) {
        int r0 = row0 + half * 64;
        int grow = r0 + arow;
        bool rowok = grow < M;
        const float4* Ar = A + (size_t)grow * 32;

        float acc[8][4];
#pragma unroll
        for (int i = 0; i < 8; i++)
#pragma unroll
            for (int j = 0; j < 4; j++) acc[i][j] = 0.f;

        for (int kt = 0; kt < 8; ++kt) {
            float4 av = rowok ? Ar[kt * 4 + (tid & 3)] : make_float4(0.f, 0.f, 0.f, 0.f);
            As[(ak + 0) * 72 + arow] = av.x;
            As[(ak + 1) * 72 + arow] = av.y;
            As[(ak + 2) * 72 + arow] = av.z;
            As[(ak + 3) * 72 + arow] = av.w;
            __syncthreads();
#pragma unroll
            for (int kk = 0; kk < 16; ++kk) {
                float4 b4 = *(float4*)&Wf[(kt * 16 + kk) * 128 + cbase];
                float4 a0 = *(float4*)&As[kk * 72 + rbase];
                float4 a1 = *(float4*)&As[kk * 72 + rbase + 4];
                float a[8] = {a0.x, a0.y, a0.z, a0.w, a1.x, a1.y, a1.z, a1.w};
#pragma unroll
                for (int i = 0; i < 8; i++) {
                    acc[i][0] += a[i] * b4.x;
                    acc[i][1] += a[i] * b4.y;
                    acc[i][2] += a[i] * b4.z;
                    acc[i][3] += a[i] * b4.w;
                }
            }
            __syncthreads();
        }

        float4 bv = make_float4(0.f, 0.f, 0.f, 0.f);
        if (bias) bv = *(const float4*)(bias + cbase);
#pragma unroll
        for (int i = 0; i < 8; i++) {
            int r = r0 + rbase + i;
            if (r < M) {
                float4 c;
                c.x = acc[i][0] + bv.x;
                c.y = acc[i][1] + bv.y;
                c.z = acc[i][2] + bv.z;
                c.w = acc[i][3] + bv.w;
                if (RELU) {
                    c.x = fmaxf(c.x, 0.f); c.y = fmaxf(c.y, 0.f);
                    c.z = fmaxf(c.z, 0.f); c.w = fmaxf(c.w, 0.f);
                }
                *(float4*)(C + (size_t)r * DIM + cbase) = c;
            }
        }
    }
#endif
}

// ---------------- BatchNorm ----------------
__global__ void __launch_bounds__(128) k_bnstats(const float* __restrict__ h, float* __restrict__ stats) {
    int c = threadIdx.x;
    float s = 0.f, s2 = 0.f;
    for (int r = blockIdx.x; r < NN; r += gridDim.x) {
        float v = h[(size_t)r * DIM + c];
        s += v;
        s2 += v * v;
    }
    atomicAdd(&stats[c], s);
    atomicAdd(&stats[DIM + c], s2);
}

__global__ void __launch_bounds__(256) k_bnnorm(const float* __restrict__ h,
                                                const float* __restrict__ stats,
                                                const float* __restrict__ gamma,
                                                const float* __restrict__ beta,
                                                float* __restrict__ out) {
    int i = blockIdx.x * 256 + threadIdx.x;
    if (i >= NN * DIM / 4) return;
    int c = (i & 31) * 4;
    float4 v = *(const float4*)(h + (size_t)i * 4);
    float vin[4] = {v.x, v.y, v.z, v.w};
    float o[4];
#pragma unroll
    for (int j = 0; j < 4; j++) {
        float mean = stats[c + j] * (1.f / NN);
        float var = stats[DIM + c + j] * (1.f / NN) - mean * mean;
        float inv = rsqrtf(var + BN_EPS);
        o[j] = (vin[j] - mean) * inv * gamma[c + j] + beta[c + j];
    }
    *(float4*)(out + (size_t)i * 4) = make_float4(o[0], o[1], o[2], o[3]);
}

// ---------------- launch ----------------
extern "C" void kernel_launch(void* const* d_in, const int* in_sizes, int n_in,
                              void* d_out, int out_size) {
    const float* x      = (const float*)d_in[0];
    const int*   edges  = (const int*)d_in[1];
    const float* conv_W = (const float*)d_in[2];
    const float* conv_b = (const float*)d_in[3];
    const float* fc_W   = (const float*)d_in[4];
    const float* fc_b   = (const float*)d_in[5];
    const float* gamma  = (const float*)d_in[6];
    const float* beta   = (const float*)d_in[7];
    float* out = (float*)d_out;

    float *h, *m, *agg, *deg, *stats, *fceff;
    uint8_t* wbf;
    cudaGetSymbolAddress((void**)&h, g_h);
    cudaGetSymbolAddress((void**)&m, g_m);
    cudaGetSymbolAddress((void**)&agg, g_agg);
    cudaGetSymbolAddress((void**)&deg, g_deg);
    cudaGetSymbolAddress((void**)&stats, g_stats);
    cudaGetSymbolAddress((void**)&wbf, g_Wbf);
    cudaGetSymbolAddress((void**)&fceff, g_fceff);

    cudaFuncSetAttribute(k_gemm_tc<false>, cudaFuncAttributeMaxDynamicSharedMemorySize, SM_TOTAL);
    cudaFuncSetAttribute(k_gemm_tc<true>, cudaFuncAttributeMaxDynamicSharedMemorySize, SM_TOTAL);

    const int nh4 = NN * DIM / 4;

    // prep: weight bf16 hi/lo images + effective fc bias
    k_wprep<<<(12 * 16384 + 255) / 256, 256>>>(conv_W, fc_W, wbf);
    k_bprep<<<NL, 128>>>(conv_b, fc_W, fc_b, fceff);

    // degrees
    k_zero<<<(6 * NN / 4 + 255) / 256, 256>>>((float4*)deg, 6 * NN / 4);
    k_deg<<<(NR * NE + 255) / 256, 256>>>(edges, deg);
    k_degfin<<<(6 * NN + 255) / 256, 256>>>(deg);

    for (int l = 0; l < NL; ++l) {
        const float* hin = (l == 0) ? x : h;
        k_zero<<<(nh4 + 255) / 256, 256>>>((float4*)agg, nh4);
        for (int r = 0; r < NR; ++r) {
            // m = hin @ W_r (GEMM before scatter; degree scales folded into scatter)
            k_gemm_tc<false><<<MTILES, 256, SM_TOTAL>>>(
                (const float4*)hin, wbf + (size_t)(l * NR + r) * 65536, nullptr, m, NN);
            k_scatter<<<(NE * 32 + 255) / 256, 256>>>(
                m,
                edges + (size_t)(r * 2 + 0) * NE,
                edges + (size_t)(r * 2 + 1) * NE,
                deg + r * NN, deg + (NR + r) * NN, agg);
        }
        // FC + ReLU (with folded conv bias)
        k_gemm_tc<true><<<MTILES, 256, SM_TOTAL>>>(
            (const float4*)agg, wbf + (size_t)(9 + l) * 65536, fceff + (size_t)l * DIM, m, NN);
        // BatchNorm
        k_zero<<<1, 256>>>((float4*)stats, 2 * DIM / 4);
        k_bnstats<<<2048, 128>>>(m, stats);
        k_bnnorm<<<(nh4 + 255) / 256, 256>>>(m, stats,
                                             gamma + (size_t)l * DIM,
                                             beta + (size_t)l * DIM,
                                             (l == NL - 1) ? out : h);
    }
}

// round 5
// speedup vs baseline: 1.6981x; 1.6013x over previous
#include <cuda_runtime.h>
#include <cuda_bf16.h>
#include <cstdint>

#define NN 100000
#define NE 600000
#define NR 3
#define NL 3
#define DIM 128
#define BN_EPS 1e-5f

#if defined(__CUDA_ARCH_FEAT_SM103_ALL) || defined(__CUDA_ARCH_FEAT_SM100_ALL) || \
    defined(__CUDA_ARCH_FEAT_SM101_ALL) || \
    (defined(__CUDA_ARCH_FAMILY_SPECIFIC__) && (__CUDA_ARCH_FAMILY_SPECIFIC__ >= 1000)) || \
    (defined(__CUDA_ARCH_SPECIFIC__) && (__CUDA_ARCH_SPECIFIC__ >= 1000))
#define HAS_TCGEN05 1
#else
#define HAS_TCGEN05 0
#endif

// ---------------- scratch ----------------
__device__ __align__(16) float g_h[(size_t)NN * DIM];
__device__ __align__(16) float g_m[(size_t)NN * DIM];
__device__ __align__(16) float g_agg[(size_t)NN * DIM];
__device__ __align__(16) float g_dinv_o[NR * NN];
__device__ __align__(16) float g_dinv_i[NR * NN];
__device__ __align__(16) int g_cnt_in[NR * NN];
__device__ __align__(16) int g_cnt_out[NR * NN];
__device__ __align__(16) int g_cursor[NR * NN];
__device__ __align__(16) int g_excl[NR * NN];
__device__ __align__(16) int g_bsum[512];
__device__ __align__(16) int g_srcidx[NR * NE];
__device__ __align__(16) float g_stats[2 * DIM];
__device__ __align__(16) uint8_t g_Wbf[12 * 65536];
__device__ __align__(16) float g_fceff[NL * DIM];

// ---------------- PTX helpers ----------------
__device__ __forceinline__ uint32_t smem_u32(const void* p) {
    uint32_t a;
    asm("{ .reg .u64 t; cvta.to.shared.u64 t, %1; cvt.u32.u64 %0, t; }" : "=r"(a) : "l"(p));
    return a;
}

#if HAS_TCGEN05
__device__ __forceinline__ uint32_t elect_one() {
    uint32_t pred;
    asm volatile("{\n\t.reg .pred p;\n\telect.sync _|p, 0xFFFFFFFF;\n\tselp.b32 %0, 1, 0, p;\n\t}" : "=r"(pred));
    return pred;
}
#define MBARRIER_INIT(addr, cnt) \
    asm volatile("mbarrier.init.shared.b64 [%0], %1;" :: "r"((uint32_t)(addr)), "r"((uint32_t)(cnt)) : "memory")
__device__ __forceinline__ void mbar_wait(uint32_t mbar, uint32_t parity) {
    asm volatile(
        "{\n\t.reg .pred P;\n\t"
        "WL_%=:\n\t"
        "mbarrier.try_wait.parity.acquire.cta.shared::cta.b64 P, [%0], %1, 0x989680;\n\t"
        "@P bra.uni WD_%=;\n\t"
        "bra.uni WL_%=;\n\t"
        "WD_%=:\n\t}"
        :: "r"(mbar), "r"(parity) : "memory");
}
#define TCGEN05_ALLOC(smem_addr, n) \
    asm volatile("tcgen05.alloc.cta_group::1.sync.aligned.shared::cta.b32 [%0], %1;" \
                 :: "r"((uint32_t)(smem_addr)), "r"((uint32_t)(n)) : "memory")
#define TCGEN05_DEALLOC(tmem, n) \
    asm volatile("tcgen05.dealloc.cta_group::1.sync.aligned.b32 %0, %1;" :: "r"(tmem), "r"((uint32_t)(n)))
#define TCGEN05_COMMIT(mbar) \
    asm volatile("tcgen05.commit.cta_group::1.mbarrier::arrive::one.shared::cluster.b64 [%0];" \
                 :: "r"((uint32_t)(mbar)) : "memory")
#define TCGEN05_WAIT_LD() asm volatile("tcgen05.wait::ld.sync.aligned;" ::: "memory")
#define TCGEN05_FENCE_AFTER() asm volatile("tcgen05.fence::after_thread_sync;" ::: "memory")
#define FENCE_ASYNC_SHARED() asm volatile("fence.proxy.async.shared::cta;" ::: "memory")

#define TCGEN05_LD_32X32B_X32(r, tmem_addr) \
    asm volatile( \
        "tcgen05.ld.sync.aligned.32x32b.x32.b32 " \
        "{%0, %1, %2, %3, %4, %5, %6, %7, " \
        " %8, %9, %10, %11, %12, %13, %14, %15, " \
        " %16, %17, %18, %19, %20, %21, %22, %23, " \
        " %24, %25, %26, %27, %28, %29, %30, %31}, [%32];" \
        : "=r"((r)[0]),  "=r"((r)[1]),  "=r"((r)[2]),  "=r"((r)[3]), \
          "=r"((r)[4]),  "=r"((r)[5]),  "=r"((r)[6]),  "=r"((r)[7]), \
          "=r"((r)[8]),  "=r"((r)[9]),  "=r"((r)[10]), "=r"((r)[11]), \
          "=r"((r)[12]), "=r"((r)[13]), "=r"((r)[14]), "=r"((r)[15]), \
          "=r"((r)[16]), "=r"((r)[17]), "=r"((r)[18]), "=r"((r)[19]), \
          "=r"((r)[20]), "=r"((r)[21]), "=r"((r)[22]), "=r"((r)[23]), \
          "=r"((r)[24]), "=r"((r)[25]), "=r"((r)[26]), "=r"((r)[27]), \
          "=r"((r)[28]), "=r"((r)[29]), "=r"((r)[30]), "=r"((r)[31]) \
        : "r"(tmem_addr))

static constexpr uint64_t SMEM_DESC_BASE_SW128 =
    (uint64_t(2) << 61) | (uint64_t(1) << 46) | (uint64_t(64) << 32) | (uint64_t(1) << 16);
#define MAKE_SMEM_DESC(base_addr) (SMEM_DESC_BASE_SW128 | ((uint64_t)((base_addr) >> 4) & 0x3FFF))

__device__ __forceinline__ void mma_f16_ss(uint32_t d, uint64_t a, uint64_t b, uint32_t idesc, int acc) {
    asm volatile(
        "{\n\t.reg .pred p;\n\tsetp.ne.u32 p, %4, 0;\n\t"
        "tcgen05.mma.cta_group::1.kind::f16 [%0], %1, %2, %3, {%5, %5, %5, %5}, p;\n\t}"
        :: "r"(d), "l"(a), "l"(b), "r"(idesc), "r"(acc), "r"(0u) : "memory");
}
#define MMA_IDESC 0x8200490u
#endif  // HAS_TCGEN05

// Blocked SW128 atom layout for a 128x128 bf16 tile.
__host__ __device__ __forceinline__ uint32_t tile_off(int row, int col) {
    uint32_t off = (uint32_t)(((row >> 3) + ((col >> 6) << 4)) << 10) | ((row & 7) << 7) | ((col & 63) << 1);
    return off ^ ((off >> 3) & 0x70);
}

// ---------------- utility ----------------
__global__ void __launch_bounds__(256) k_zero(float4* p, int n4) {
    int i = blockIdx.x * 256 + threadIdx.x;
    if (i < n4) p[i] = make_float4(0.f, 0.f, 0.f, 0.f);
}
__global__ void __launch_bounds__(256) k_zeroi(int* p, int n) {
    int i = blockIdx.x * 256 + threadIdx.x;
    if (i < n) p[i] = 0;
}

// ---------------- degree counts ----------------
__global__ void __launch_bounds__(256) k_cnt(const int* __restrict__ edges,
                                             int* __restrict__ cnt_out, int* __restrict__ cnt_in) {
    int i = blockIdx.x * 256 + threadIdx.x;
    if (i >= NR * NE) return;
    int r = i / NE;
    int e = i - r * NE;
    int s = edges[(size_t)(r * 2 + 0) * NE + e];
    int d = edges[(size_t)(r * 2 + 1) * NE + e];
    atomicAdd(&cnt_out[r * NN + s], 1);
    atomicAdd(&cnt_in[r * NN + d], 1);
}
__global__ void __launch_bounds__(256) k_dinv(const int* __restrict__ cnt_out, const int* __restrict__ cnt_in,
                                              float* __restrict__ dinv_o, float* __restrict__ dinv_i) {
    int i = blockIdx.x * 256 + threadIdx.x;
    if (i >= NR * NN) return;
    dinv_o[i] = rsqrtf(fmaxf((float)cnt_out[i], 1.f));
    dinv_i[i] = rsqrtf(fmaxf((float)cnt_in[i], 1.f));
}

// ---------------- exclusive scan (3 kernels) over flattened cnt_in[NR*NN] ----------------
__global__ void __launch_bounds__(1024) k_scan1(const int* __restrict__ cnt, int* __restrict__ excl,
                                                int* __restrict__ bsum, int N) {
    int i = blockIdx.x * 1024 + threadIdx.x;
    int lane = threadIdx.x & 31, warp = threadIdx.x >> 5;
    int x = (i < N) ? cnt[i] : 0;
    int v = x;
#pragma unroll
    for (int o = 1; o < 32; o <<= 1) { int y = __shfl_up_sync(~0u, v, o); if (lane >= o) v += y; }
    __shared__ int ws[32];
    if (lane == 31) ws[warp] = v;
    __syncthreads();
    if (warp == 0) {
        int w = ws[lane];
#pragma unroll
        for (int o = 1; o < 32; o <<= 1) { int y = __shfl_up_sync(~0u, w, o); if (lane >= o) w += y; }
        ws[lane] = w;
    }
    __syncthreads();
    int wexcl = (warp == 0) ? 0 : ws[warp - 1];
    if (i < N) excl[i] = wexcl + v - x;
    if (threadIdx.x == 1023) bsum[blockIdx.x] = ws[31];
}
__global__ void __launch_bounds__(512) k_scan2(int* __restrict__ bsum, int nb) {
    __shared__ int s[512];
    int tid = threadIdx.x;
    int v = (tid < nb) ? bsum[tid] : 0;
    s[tid] = v;
    __syncthreads();
    for (int o = 1; o < 512; o <<= 1) {
        int y = (tid >= o) ? s[tid - o] : 0;
        __syncthreads();
        s[tid] += y;
        __syncthreads();
    }
    if (tid < nb) bsum[tid] = s[tid] - v;   // exclusive
}
__global__ void __launch_bounds__(1024) k_scan3(int* __restrict__ excl, const int* __restrict__ bsum, int N) {
    int i = blockIdx.x * 1024 + threadIdx.x;
    if (i < N) excl[i] += bsum[blockIdx.x];
}

// ---------------- CSR placement: src ids grouped by dst ----------------
__global__ void __launch_bounds__(256) k_place(const int* __restrict__ edges, const int* __restrict__ excl,
                                               int* __restrict__ cursor, int* __restrict__ srcidx) {
    int i = blockIdx.x * 256 + threadIdx.x;
    if (i >= NR * NE) return;
    int r = i / NE;
    int e = i - r * NE;
    int s = edges[(size_t)(r * 2 + 0) * NE + e];
    int d = edges[(size_t)(r * 2 + 1) * NE + e];
    int pos = atomicAdd(&cursor[r * NN + d], 1);
    srcidx[excl[r * NN + d] + pos] = s;
}

// ---------------- weight prep ----------------
__global__ void __launch_bounds__(256) k_wprep(const float* __restrict__ convW,
                                               const float* __restrict__ fcW,
                                               uint8_t* __restrict__ wbf) {
    int idx = blockIdx.x * 256 + threadIdx.x;
    if (idx >= 12 * 16384) return;
    int w = idx >> 14;
    int e = idx & 16383;
    int k = e >> 7, n = e & 127;
    const float* W = (w < 9) ? (convW + (size_t)w * 16384) : (fcW + (size_t)(w - 9) * 16384);
    float v = W[e];
    __nv_bfloat16 hi = __float2bfloat16(v);
    __nv_bfloat16 lo = __float2bfloat16(v - __bfloat162float(hi));
    uint32_t off = tile_off(n, k);
    *(__nv_bfloat16*)(wbf + (size_t)w * 65536 + off) = hi;
    *(__nv_bfloat16*)(wbf + (size_t)w * 65536 + 32768 + off) = lo;
}
__global__ void __launch_bounds__(128) k_bprep(const float* __restrict__ conv_b,
                                               const float* __restrict__ fc_W,
                                               const float* __restrict__ fc_b,
                                               float* __restrict__ fceff) {
    __shared__ float bs[DIM];
    int l = blockIdx.x, n = threadIdx.x;
    bs[n] = conv_b[(size_t)(l * 3 + 0) * DIM + n] + conv_b[(size_t)(l * 3 + 1) * DIM + n] +
            conv_b[(size_t)(l * 3 + 2) * DIM + n];
    __syncthreads();
    float acc = fc_b[(size_t)l * DIM + n];
    for (int k = 0; k < DIM; k++) acc += bs[k] * fc_W[(size_t)l * DIM * DIM + (size_t)k * DIM + n];
    fceff[(size_t)l * DIM + n] = acc;
}

// ---------------- gather aggregation: agg[d] (+)= dinv_i[d] * sum_{e: dst=d} m[src_e] ----------------
template <bool FIRST>
__global__ void __launch_bounds__(256) k_gather(const float* __restrict__ m,
                                                const int* __restrict__ srcidx,
                                                const int* __restrict__ excl,
                                                const int* __restrict__ cnt,
                                                const float* __restrict__ dinv_i,
                                                float* __restrict__ agg) {
    int node = (blockIdx.x * 256 + threadIdx.x) >> 5;
    int lane = threadIdx.x & 31;
    if (node >= NN) return;
    int n = cnt[node];
    int base = excl[node];
    float ax = 0.f, ay = 0.f, az = 0.f, aw = 0.f;
    for (int c0 = 0; c0 < n; c0 += 32) {
        int sl = (c0 + lane < n) ? srcidx[base + c0 + lane] : 0;
        int lim = min(32, n - c0);
        for (int i = 0; i < lim; i++) {
            int s = __shfl_sync(~0u, sl, i);
            float4 v = *(const float4*)(m + (size_t)s * DIM + lane * 4);
            ax += v.x; ay += v.y; az += v.z; aw += v.w;
        }
    }
    float sc = dinv_i[node];
    float* p = agg + (size_t)node * DIM + lane * 4;
    float4 o;
    o.x = ax * sc; o.y = ay * sc; o.z = az * sc; o.w = aw * sc;
    if (!FIRST) {
        float4 old = *(float4*)p;
        o.x += old.x; o.y += old.y; o.z += old.z; o.w += old.w;
    }
    *(float4*)p = o;
}

// ---------------- GEMM: C[M,128] = rowscale .* (A[M,128] @ W[128,128]) (+bias)(+relu) ----------------
// M=256 per CTA: two 128-row MMA groups share one weight copy; bf16 hi/lo 3-pass.
#define SM_TMEM 0
#define SM_MBAR 8
#define SM_A 1024                         // per tile t: hi at SM_A + t*65536, lo at +32768
#define SM_W (SM_A + 131072)              // hi 32KB + lo 32KB
#define SM_TOTAL (SM_W + 65536)           // 197632 bytes

template <bool RELU>
__global__ void __launch_bounds__(256, 1) k_gemm_tc(const float4* __restrict__ A,
                                                    const uint8_t* __restrict__ Wimg,
                                                    const float* __restrict__ bias,
                                                    const float* __restrict__ rowscale,
                                                    float* __restrict__ C, int M) {
    extern __shared__ char sm[];
    int tid = threadIdx.x, wid = tid >> 5, lid = tid & 31;
    int row0 = blockIdx.x * 256;

#if HAS_TCGEN05
    uint32_t smb = smem_u32(sm);
    if (tid == 0) MBARRIER_INIT(smb + SM_MBAR, 1);
    if (wid == 0) { TCGEN05_ALLOC(smb + SM_TMEM, 256); }
    __syncthreads();

    // weight hi+lo images -> smem
    {
        const float4* Wv = (const float4*)Wimg;
        float4* Bv = (float4*)(sm + SM_W);
#pragma unroll
        for (int i = 0; i < 16; i++) Bv[tid + i * 256] = Wv[tid + i * 256];
    }

    // A: 256 rows, fp32 -> bf16 hi/lo swizzled
    for (int i = tid; i < 8192; i += 256) {
        int row = i >> 5;                  // 0..255
        int c4 = i & 31;
        int t = row >> 7, lrow = row & 127;
        int grow = row0 + row;
        float4 v = make_float4(0.f, 0.f, 0.f, 0.f);
        if (grow < M) v = A[(size_t)grow * 32 + c4];
        __nv_bfloat162 h01 = __floats2bfloat162_rn(v.x, v.y);
        __nv_bfloat162 h23 = __floats2bfloat162_rn(v.z, v.w);
        float lx = v.x - __bfloat162float(h01.x);
        float ly = v.y - __bfloat162float(h01.y);
        float lz = v.z - __bfloat162float(h23.x);
        float lw = v.w - __bfloat162float(h23.y);
        __nv_bfloat162 l01 = __floats2bfloat162_rn(lx, ly);
        __nv_bfloat162 l23 = __floats2bfloat162_rn(lz, lw);
        uint32_t off = tile_off(lrow, c4 * 4);
        uint2 hv, lv;
        hv.x = *(uint32_t*)&h01; hv.y = *(uint32_t*)&h23;
        lv.x = *(uint32_t*)&l01; lv.y = *(uint32_t*)&l23;
        *(uint2*)(sm + SM_A + t * 65536 + off) = hv;
        *(uint2*)(sm + SM_A + t * 65536 + 32768 + off) = lv;
    }

    FENCE_ASYNC_SHARED();
    __syncthreads();

    uint32_t tmem;
    asm volatile("ld.shared.b32 %0, [%1];" : "=r"(tmem) : "r"(smb + SM_TMEM));

    if (wid == 0 && elect_one()) {
        uint64_t bH = MAKE_SMEM_DESC(smb + SM_W);
        uint64_t bL = MAKE_SMEM_DESC(smb + SM_W + 32768);
#pragma unroll
        for (int t = 0; t < 2; t++) {
            uint64_t aH = MAKE_SMEM_DESC(smb + SM_A + t * 65536);
            uint64_t aL = MAKE_SMEM_DESC(smb + SM_A + t * 65536 + 32768);
            uint64_t ad[3] = {aH, aH, aL};
            uint64_t bd[3] = {bH, bL, bH};
#pragma unroll
            for (int p = 0; p < 3; p++) {
#pragma unroll
                for (int s = 0; s < 8; s++) {
                    uint64_t o = (s < 4) ? (uint64_t)(s * 2) : (uint64_t)(1024 + (s - 4) * 2);
                    mma_f16_ss(tmem + t * 128, ad[p] + o, bd[p] + o, MMA_IDESC, !(p == 0 && s == 0));
                }
            }
        }
        TCGEN05_COMMIT(smb + SM_MBAR);
    }

    mbar_wait(smb + SM_MBAR, 0);
    TCGEN05_FENCE_AFTER();

    // epilogue: per tile, rows by subpartition (wid&3), col halves by (wid>>2)
#pragma unroll
    for (int t = 0; t < 2; t++) {
        int rb = t * 128 + (wid & 3) * 32 + lid;
        int grow = row0 + rb;
        float rs = 1.f;
        if (rowscale && grow < M) rs = rowscale[grow];
        int chalf = (wid >> 2) * 64;
#pragma unroll
        for (int h = 0; h < 2; h++) {
            int cb = chalf + h * 32;
            uint32_t dr[32];
            TCGEN05_LD_32X32B_X32(dr, tmem + t * 128 + cb);
            TCGEN05_WAIT_LD();
            if (grow < M) {
                float* op = C + (size_t)grow * DIM + cb;
#pragma unroll
                for (int j = 0; j < 8; j++) {
                    float4 c;
                    c.x = __uint_as_float(dr[4 * j + 0]);
                    c.y = __uint_as_float(dr[4 * j + 1]);
                    c.z = __uint_as_float(dr[4 * j + 2]);
                    c.w = __uint_as_float(dr[4 * j + 3]);
                    if (bias) {
                        float4 bv = *(const float4*)(bias + cb + 4 * j);
                        c.x += bv.x; c.y += bv.y; c.z += bv.z; c.w += bv.w;
                    }
                    c.x *= rs; c.y *= rs; c.z *= rs; c.w *= rs;
                    if (RELU) {
                        c.x = fmaxf(c.x, 0.f); c.y = fmaxf(c.y, 0.f);
                        c.z = fmaxf(c.z, 0.f); c.w = fmaxf(c.w, 0.f);
                    }
                    *(float4*)(op + 4 * j) = c;
                }
            }
        }
    }

    __syncthreads();
    if (wid == 0) TCGEN05_DEALLOC(tmem, 256);

#else  // ---------------- fallback: scalar FFMA (non-'a' target) ----------------
    float* Wf = (float*)sm;                 // [128][128] fp32
    float* As = Wf + 16384;                 // [16][72] staged

    for (int i = tid; i < 16384; i += 256) {
        int k = i >> 7, n = i & 127;
        uint32_t off = tile_off(n, k);
        float hi = __bfloat162float(*(const __nv_bfloat16*)(Wimg + off));
        float lo = __bfloat162float(*(const __nv_bfloat16*)(Wimg + 32768 + off));
        Wf[i] = hi + lo;
    }
    __syncthreads();

    int rbase = (tid >> 5) * 8;
    int cbase = (tid & 31) * 4;
    int arow = tid >> 2;
    int ak = (tid & 3) * 4;

    for (int half = 0; half < 4; half++) {
        int r0 = row0 + half * 64;
        int grow = r0 + arow;
        bool rowok = grow < M;
        const float4* Ar = A + (size_t)grow * 32;

        float acc[8][4];
#pragma unroll
        for (int i = 0; i < 8; i++)
#pragma unroll
            for (int j = 0; j < 4; j++) acc[i][j] = 0.f;

        for (int kt = 0; kt < 8; ++kt) {
            float4 av = rowok ? Ar[kt * 4 + (tid & 3)] : make_float4(0.f, 0.f, 0.f, 0.f);
            As[(ak + 0) * 72 + arow] = av.x;
            As[(ak + 1) * 72 + arow] = av.y;
            As[(ak + 2) * 72 + arow] = av.z;
            As[(ak + 3) * 72 + arow] = av.w;
            __syncthreads();
#pragma unroll
            for (int kk = 0; kk < 16; ++kk) {
                float4 b4 = *(float4*)&Wf[(kt * 16 + kk) * 128 + cbase];
                float4 a0 = *(float4*)&As[kk * 72 + rbase];
                float4 a1 = *(float4*)&As[kk * 72 + rbase + 4];
                float a[8] = {a0.x, a0.y, a0.z, a0.w, a1.x, a1.y, a1.z, a1.w};
#pragma unroll
                for (int i = 0; i < 8; i++) {
                    acc[i][0] += a[i] * b4.x;
                    acc[i][1] += a[i] * b4.y;
                    acc[i][2] += a[i] * b4.z;
                    acc[i][3] += a[i] * b4.w;
                }
            }
            __syncthreads();
        }

        float4 bv = make_float4(0.f, 0.f, 0.f, 0.f);
        if (bias) bv = *(const float4*)(bias + cbase);
#pragma unroll
        for (int i = 0; i < 8; i++) {
            int r = r0 + rbase + i;
            if (r < M) {
                float rs = rowscale ? rowscale[r] : 1.f;
                float4 c;
                c.x = (acc[i][0] + bv.x) * rs;
                c.y = (acc[i][1] + bv.y) * rs;
                c.z = (acc[i][2] + bv.z) * rs;
                c.w = (acc[i][3] + bv.w) * rs;
                if (RELU) {
                    c.x = fmaxf(c.x, 0.f); c.y = fmaxf(c.y, 0.f);
                    c.z = fmaxf(c.z, 0.f); c.w = fmaxf(c.w, 0.f);
                }
                *(float4*)(C + (size_t)r * DIM + cbase) = c;
            }
        }
    }
#endif
}

// ---------------- BatchNorm ----------------
__global__ void __launch_bounds__(128) k_bnstats(const float* __restrict__ h, float* __restrict__ stats) {
    int c = threadIdx.x;
    float s = 0.f, s2 = 0.f;
    for (int r = blockIdx.x; r < NN; r += gridDim.x) {
        float v = h[(size_t)r * DIM + c];
        s += v;
        s2 += v * v;
    }
    atomicAdd(&stats[c], s);
    atomicAdd(&stats[DIM + c], s2);
}
__global__ void __launch_bounds__(256) k_bnnorm(const float* __restrict__ h,
                                                const float* __restrict__ stats,
                                                const float* __restrict__ gamma,
                                                const float* __restrict__ beta,
                                                float* __restrict__ out) {
    int i = blockIdx.x * 256 + threadIdx.x;
    if (i >= NN * DIM / 4) return;
    int c = (i & 31) * 4;
    float4 v = *(const float4*)(h + (size_t)i * 4);
    float vin[4] = {v.x, v.y, v.z, v.w};
    float o[4];
#pragma unroll
    for (int j = 0; j < 4; j++) {
        float mean = stats[c + j] * (1.f / NN);
        float var = stats[DIM + c + j] * (1.f / NN) - mean * mean;
        float inv = rsqrtf(var + BN_EPS);
        o[j] = (vin[j] - mean) * inv * gamma[c + j] + beta[c + j];
    }
    *(float4*)(out + (size_t)i * 4) = make_float4(o[0], o[1], o[2], o[3]);
}

// ---------------- launch ----------------
extern "C" void kernel_launch(void* const* d_in, const int* in_sizes, int n_in,
                              void* d_out, int out_size) {
    const float* x      = (const float*)d_in[0];
    const int*   edges  = (const int*)d_in[1];
    const float* conv_W = (const float*)d_in[2];
    const float* conv_b = (const float*)d_in[3];
    const float* fc_W   = (const float*)d_in[4];
    const float* fc_b   = (const float*)d_in[5];
    const float* gamma  = (const float*)d_in[6];
    const float* beta   = (const float*)d_in[7];
    float* out = (float*)d_out;

    float *h, *m, *agg, *dinv_o, *dinv_i, *stats, *fceff;
    int *cnt_in, *cnt_out, *cursor, *excl, *bsum, *srcidx;
    uint8_t* wbf;
    cudaGetSymbolAddress((void**)&h, g_h);
    cudaGetSymbolAddress((void**)&m, g_m);
    cudaGetSymbolAddress((void**)&agg, g_agg);
    cudaGetSymbolAddress((void**)&dinv_o, g_dinv_o);
    cudaGetSymbolAddress((void**)&dinv_i, g_dinv_i);
    cudaGetSymbolAddress((void**)&cnt_in, g_cnt_in);
    cudaGetSymbolAddress((void**)&cnt_out, g_cnt_out);
    cudaGetSymbolAddress((void**)&cursor, g_cursor);
    cudaGetSymbolAddress((void**)&excl, g_excl);
    cudaGetSymbolAddress((void**)&bsum, g_bsum);
    cudaGetSymbolAddress((void**)&srcidx, g_srcidx);
    cudaGetSymbolAddress((void**)&stats, g_stats);
    cudaGetSymbolAddress((void**)&wbf, g_Wbf);
    cudaGetSymbolAddress((void**)&fceff, g_fceff);

    cudaFuncSetAttribute(k_gemm_tc<false>, cudaFuncAttributeMaxDynamicSharedMemorySize, SM_TOTAL);
    cudaFuncSetAttribute(k_gemm_tc<true>, cudaFuncAttributeMaxDynamicSharedMemorySize, SM_TOTAL);

    const int nh4 = NN * DIM / 4;
    const int NSC = NR * NN;                       // 300000
    const int NB1 = (NSC + 1023) / 1024;           // 293

    // ---- prep ----
    k_wprep<<<(12 * 16384 + 255) / 256, 256>>>(conv_W, fc_W, wbf);
    k_bprep<<<NL, 128>>>(conv_b, fc_W, fc_b, fceff);

    k_zeroi<<<(NSC + 255) / 256, 256>>>(cnt_in, NSC);
    k_zeroi<<<(NSC + 255) / 256, 256>>>(cnt_out, NSC);
    k_zeroi<<<(NSC + 255) / 256, 256>>>(cursor, NSC);
    k_cnt<<<(NR * NE + 255) / 256, 256>>>(edges, cnt_out, cnt_in);
    k_dinv<<<(NSC + 255) / 256, 256>>>(cnt_out, cnt_in, dinv_o, dinv_i);

    k_scan1<<<NB1, 1024>>>(cnt_in, excl, bsum, NSC);
    k_scan2<<<1, 512>>>(bsum, NB1);
    k_scan3<<<NB1, 1024>>>(excl, bsum, NSC);
    k_place<<<(NR * NE + 255) / 256, 256>>>(edges, excl, cursor, srcidx);

    const int GGRID = (NN * 32 + 255) / 256;       // one warp per node
    const int MGRID = (NN + 255) / 256;            // 391

    for (int l = 0; l < NL; ++l) {
        const float* hin = (l == 0) ? x : h;
        for (int r = 0; r < NR; ++r) {
            // m = dinv_o .* (hin @ W_r)
            k_gemm_tc<false><<<MGRID, 256, SM_TOTAL>>>(
                (const float4*)hin, wbf + (size_t)(l * NR + r) * 65536,
                nullptr, dinv_o + r * NN, m, NN);
            if (r == 0)
                k_gather<true><<<GGRID, 256>>>(m, srcidx, excl + r * NN, cnt_in + r * NN,
                                               dinv_i + r * NN, agg);
            else
                k_gather<false><<<GGRID, 256>>>(m, srcidx, excl + r * NN, cnt_in + r * NN,
                                                dinv_i + r * NN, agg);
        }
        // FC + ReLU (conv biases folded into fceff)
        k_gemm_tc<true><<<MGRID, 256, SM_TOTAL>>>(
            (const float4*)agg, wbf + (size_t)(9 + l) * 65536,
            fceff + (size_t)l * DIM, nullptr, m, NN);
        // BatchNorm
        k_zero<<<1, 256>>>((float4*)stats, 2 * DIM / 4);
        k_bnstats<<<1024, 128>>>(m, stats);
        k_bnnorm<<<(nh4 + 255) / 256, 256>>>(m, stats,
                                             gamma + (size_t)l * DIM,
                                             beta + (size_t)l * DIM,
                                             (l == NL - 1) ? out : h);
    }
}

// round 6
// speedup vs baseline: 2.2209x; 1.3079x over previous
#include <cuda_runtime.h>
#include <cuda_bf16.h>
#include <cstdint>

#define NN 100000
#define NE 600000
#define NR 3
#define NL 3
#define DIM 128
#define BN_EPS 1e-5f

#if defined(__CUDA_ARCH_FEAT_SM103_ALL) || defined(__CUDA_ARCH_FEAT_SM100_ALL) || \
    defined(__CUDA_ARCH_FEAT_SM101_ALL) || \
    (defined(__CUDA_ARCH_FAMILY_SPECIFIC__) && (__CUDA_ARCH_FAMILY_SPECIFIC__ >= 1000)) || \
    (defined(__CUDA_ARCH_SPECIFIC__) && (__CUDA_ARCH_SPECIFIC__ >= 1000))
#define HAS_TCGEN05 1
#else
#define HAS_TCGEN05 0
#endif

// ---------------- scratch ----------------
__device__ __align__(16) float g_h[(size_t)NN * DIM];
__device__ __align__(16) float g_m0[(size_t)NN * DIM];
__device__ __align__(16) float g_m1[(size_t)NN * DIM];
__device__ __align__(16) float g_m2[(size_t)NN * DIM];
__device__ __align__(16) float g_agg[(size_t)NN * DIM];
__device__ __align__(16) float g_dinv_o[NR * NN];
__device__ __align__(16) float g_dinv_i[NR * NN];
__device__ __align__(16) int g_cnt_in[NR * NN];
__device__ __align__(16) int g_cnt_out[NR * NN];
__device__ __align__(16) int g_cursor[NR * NN];
__device__ __align__(16) int g_excl[NR * NN];
__device__ __align__(16) int g_bsum[512];
__device__ __align__(16) int g_srcidx[NR * NE];
__device__ __align__(16) float g_stats[2 * DIM];
__device__ __align__(16) uint8_t g_Wbf[12 * 65536];
__device__ __align__(16) float g_fceff[NL * DIM];

// ---------------- PTX helpers ----------------
__device__ __forceinline__ uint32_t smem_u32(const void* p) {
    uint32_t a;
    asm("{ .reg .u64 t; cvta.to.shared.u64 t, %1; cvt.u32.u64 %0, t; }" : "=r"(a) : "l"(p));
    return a;
}

#if HAS_TCGEN05
__device__ __forceinline__ uint32_t elect_one() {
    uint32_t pred;
    asm volatile("{\n\t.reg .pred p;\n\telect.sync _|p, 0xFFFFFFFF;\n\tselp.b32 %0, 1, 0, p;\n\t}" : "=r"(pred));
    return pred;
}
#define MBARRIER_INIT(addr, cnt) \
    asm volatile("mbarrier.init.shared.b64 [%0], %1;" :: "r"((uint32_t)(addr)), "r"((uint32_t)(cnt)) : "memory")
__device__ __forceinline__ void mbar_wait(uint32_t mbar, uint32_t parity) {
    asm volatile(
        "{\n\t.reg .pred P;\n\t"
        "WL_%=:\n\t"
        "mbarrier.try_wait.parity.acquire.cta.shared::cta.b64 P, [%0], %1, 0x989680;\n\t"
        "@P bra.uni WD_%=;\n\t"
        "bra.uni WL_%=;\n\t"
        "WD_%=:\n\t}"
        :: "r"(mbar), "r"(parity) : "memory");
}
#define TCGEN05_ALLOC(smem_addr, n) \
    asm volatile("tcgen05.alloc.cta_group::1.sync.aligned.shared::cta.b32 [%0], %1;" \
                 :: "r"((uint32_t)(smem_addr)), "r"((uint32_t)(n)) : "memory")
#define TCGEN05_DEALLOC(tmem, n) \
    asm volatile("tcgen05.dealloc.cta_group::1.sync.aligned.b32 %0, %1;" :: "r"(tmem), "r"((uint32_t)(n)))
#define TCGEN05_COMMIT(mbar) \
    asm volatile("tcgen05.commit.cta_group::1.mbarrier::arrive::one.shared::cluster.b64 [%0];" \
                 :: "r"((uint32_t)(mbar)) : "memory")
#define TCGEN05_WAIT_LD() asm volatile("tcgen05.wait::ld.sync.aligned;" ::: "memory")
#define TCGEN05_FENCE_AFTER() asm volatile("tcgen05.fence::after_thread_sync;" ::: "memory")
#define FENCE_ASYNC_SHARED() asm volatile("fence.proxy.async.shared::cta;" ::: "memory")

#define TCGEN05_LD_32X32B_X32(r, tmem_addr) \
    asm volatile( \
        "tcgen05.ld.sync.aligned.32x32b.x32.b32 " \
        "{%0, %1, %2, %3, %4, %5, %6, %7, " \
        " %8, %9, %10, %11, %12, %13, %14, %15, " \
        " %16, %17, %18, %19, %20, %21, %22, %23, " \
        " %24, %25, %26, %27, %28, %29, %30, %31}, [%32];" \
        : "=r"((r)[0]),  "=r"((r)[1]),  "=r"((r)[2]),  "=r"((r)[3]), \
          "=r"((r)[4]),  "=r"((r)[5]),  "=r"((r)[6]),  "=r"((r)[7]), \
          "=r"((r)[8]),  "=r"((r)[9]),  "=r"((r)[10]), "=r"((r)[11]), \
          "=r"((r)[12]), "=r"((r)[13]), "=r"((r)[14]), "=r"((r)[15]), \
          "=r"((r)[16]), "=r"((r)[17]), "=r"((r)[18]), "=r"((r)[19]), \
          "=r"((r)[20]), "=r"((r)[21]), "=r"((r)[22]), "=r"((r)[23]), \
          "=r"((r)[24]), "=r"((r)[25]), "=r"((r)[26]), "=r"((r)[27]), \
          "=r"((r)[28]), "=r"((r)[29]), "=r"((r)[30]), "=r"((r)[31]) \
        : "r"(tmem_addr))

static constexpr uint64_t SMEM_DESC_BASE_SW128 =
    (uint64_t(2) << 61) | (uint64_t(1) << 46) | (uint64_t(64) << 32) | (uint64_t(1) << 16);
#define MAKE_SMEM_DESC(base_addr) (SMEM_DESC_BASE_SW128 | ((uint64_t)((base_addr) >> 4) & 0x3FFF))

__device__ __forceinline__ void mma_f16_ss(uint32_t d, uint64_t a, uint64_t b, uint32_t idesc, int acc) {
    asm volatile(
        "{\n\t.reg .pred p;\n\tsetp.ne.u32 p, %4, 0;\n\t"
        "tcgen05.mma.cta_group::1.kind::f16 [%0], %1, %2, %3, {%5, %5, %5, %5}, p;\n\t}"
        :: "r"(d), "l"(a), "l"(b), "r"(idesc), "r"(acc), "r"(0u) : "memory");
}
#define MMA_IDESC 0x8200490u
#endif  // HAS_TCGEN05

// Blocked SW128 atom layout for a 128x128 bf16 tile.
__host__ __device__ __forceinline__ uint32_t tile_off(int row, int col) {
    uint32_t off = (uint32_t)(((row >> 3) + ((col >> 6) << 4)) << 10) | ((row & 7) << 7) | ((col & 63) << 1);
    return off ^ ((off >> 3) & 0x70);
}

// bf16 hi/lo split of a float4, store swizzled to two smem images
__device__ __forceinline__ void split_store(char* base_hi, char* base_lo, uint32_t off, float4 v) {
    __nv_bfloat162 h01 = __floats2bfloat162_rn(v.x, v.y);
    __nv_bfloat162 h23 = __floats2bfloat162_rn(v.z, v.w);
    float lx = v.x - __bfloat162float(h01.x);
    float ly = v.y - __bfloat162float(h01.y);
    float lz = v.z - __bfloat162float(h23.x);
    float lw = v.w - __bfloat162float(h23.y);
    __nv_bfloat162 l01 = __floats2bfloat162_rn(lx, ly);
    __nv_bfloat162 l23 = __floats2bfloat162_rn(lz, lw);
    uint2 hv, lv;
    hv.x = *(uint32_t*)&h01; hv.y = *(uint32_t*)&h23;
    lv.x = *(uint32_t*)&l01; lv.y = *(uint32_t*)&l23;
    *(uint2*)(base_hi + off) = hv;
    *(uint2*)(base_lo + off) = lv;
}

// ---------------- utility ----------------
__global__ void __launch_bounds__(256) k_zero(float4* p, int n4) {
    int i = blockIdx.x * 256 + threadIdx.x;
    if (i < n4) p[i] = make_float4(0.f, 0.f, 0.f, 0.f);
}
__global__ void __launch_bounds__(256) k_zeroi(int* p, int n) {
    int i = blockIdx.x * 256 + threadIdx.x;
    if (i < n) p[i] = 0;
}

// ---------------- degree counts / CSR build ----------------
__global__ void __launch_bounds__(256) k_cnt(const int* __restrict__ edges,
                                             int* __restrict__ cnt_out, int* __restrict__ cnt_in) {
    int i = blockIdx.x * 256 + threadIdx.x;
    if (i >= NR * NE) return;
    int r = i / NE;
    int e = i - r * NE;
    int s = edges[(size_t)(r * 2 + 0) * NE + e];
    int d = edges[(size_t)(r * 2 + 1) * NE + e];
    atomicAdd(&cnt_out[r * NN + s], 1);
    atomicAdd(&cnt_in[r * NN + d], 1);
}
__global__ void __launch_bounds__(256) k_dinv(const int* __restrict__ cnt_out, const int* __restrict__ cnt_in,
                                              float* __restrict__ dinv_o, float* __restrict__ dinv_i) {
    int i = blockIdx.x * 256 + threadIdx.x;
    if (i >= NR * NN) return;
    dinv_o[i] = rsqrtf(fmaxf((float)cnt_out[i], 1.f));
    dinv_i[i] = rsqrtf(fmaxf((float)cnt_in[i], 1.f));
}
__global__ void __launch_bounds__(1024) k_scan1(const int* __restrict__ cnt, int* __restrict__ excl,
                                                int* __restrict__ bsum, int N) {
    int i = blockIdx.x * 1024 + threadIdx.x;
    int lane = threadIdx.x & 31, warp = threadIdx.x >> 5;
    int x = (i < N) ? cnt[i] : 0;
    int v = x;
#pragma unroll
    for (int o = 1; o < 32; o <<= 1) { int y = __shfl_up_sync(~0u, v, o); if (lane >= o) v += y; }
    __shared__ int ws[32];
    if (lane == 31) ws[warp] = v;
    __syncthreads();
    if (warp == 0) {
        int w = ws[lane];
#pragma unroll
        for (int o = 1; o < 32; o <<= 1) { int y = __shfl_up_sync(~0u, w, o); if (lane >= o) w += y; }
        ws[lane] = w;
    }
    __syncthreads();
    int wexcl = (warp == 0) ? 0 : ws[warp - 1];
    if (i < N) excl[i] = wexcl + v - x;
    if (threadIdx.x == 1023) bsum[blockIdx.x] = ws[31];
}
__global__ void __launch_bounds__(512) k_scan2(int* __restrict__ bsum, int nb) {
    __shared__ int s[512];
    int tid = threadIdx.x;
    int v = (tid < nb) ? bsum[tid] : 0;
    s[tid] = v;
    __syncthreads();
    for (int o = 1; o < 512; o <<= 1) {
        int y = (tid >= o) ? s[tid - o] : 0;
        __syncthreads();
        s[tid] += y;
        __syncthreads();
    }
    if (tid < nb) bsum[tid] = s[tid] - v;
}
__global__ void __launch_bounds__(1024) k_scan3(int* __restrict__ excl, const int* __restrict__ bsum, int N) {
    int i = blockIdx.x * 1024 + threadIdx.x;
    if (i < N) excl[i] += bsum[blockIdx.x];
}
__global__ void __launch_bounds__(256) k_place(const int* __restrict__ edges, const int* __restrict__ excl,
                                               int* __restrict__ cursor, int* __restrict__ srcidx) {
    int i = blockIdx.x * 256 + threadIdx.x;
    if (i >= NR * NE) return;
    int r = i / NE;
    int e = i - r * NE;
    int s = edges[(size_t)(r * 2 + 0) * NE + e];
    int d = edges[(size_t)(r * 2 + 1) * NE + e];
    int pos = atomicAdd(&cursor[r * NN + d], 1);
    srcidx[excl[r * NN + d] + pos] = s;
}

// ---------------- weight / bias prep ----------------
__global__ void __launch_bounds__(256) k_wprep(const float* __restrict__ convW,
                                               const float* __restrict__ fcW,
                                               uint8_t* __restrict__ wbf) {
    int idx = blockIdx.x * 256 + threadIdx.x;
    if (idx >= 12 * 16384) return;
    int w = idx >> 14;
    int e = idx & 16383;
    int k = e >> 7, n = e & 127;
    const float* W = (w < 9) ? (convW + (size_t)w * 16384) : (fcW + (size_t)(w - 9) * 16384);
    float v = W[e];
    __nv_bfloat16 hi = __float2bfloat16(v);
    __nv_bfloat16 lo = __float2bfloat16(v - __bfloat162float(hi));
    uint32_t off = tile_off(n, k);
    *(__nv_bfloat16*)(wbf + (size_t)w * 65536 + off) = hi;
    *(__nv_bfloat16*)(wbf + (size_t)w * 65536 + 32768 + off) = lo;
}
__global__ void __launch_bounds__(128) k_bprep(const float* __restrict__ conv_b,
                                               const float* __restrict__ fc_W,
                                               const float* __restrict__ fc_b,
                                               float* __restrict__ fceff) {
    __shared__ float bs[DIM];
    int l = blockIdx.x, n = threadIdx.x;
    bs[n] = conv_b[(size_t)(l * 3 + 0) * DIM + n] + conv_b[(size_t)(l * 3 + 1) * DIM + n] +
            conv_b[(size_t)(l * 3 + 2) * DIM + n];
    __syncthreads();
    float acc = fc_b[(size_t)l * DIM + n];
    for (int k = 0; k < DIM; k++) acc += bs[k] * fc_W[(size_t)l * DIM * DIM + (size_t)k * DIM + n];
    fceff[(size_t)l * DIM + n] = acc;
}

// ---------------- fused gather (3 relations): agg[d] = sum_r dinv_i_r[d] * sum_{e} m_r[src_e] ----------------
__global__ void __launch_bounds__(256) k_gather3(const float* __restrict__ m0,
                                                 const float* __restrict__ m1,
                                                 const float* __restrict__ m2,
                                                 const int* __restrict__ srcidx,
                                                 const int* __restrict__ excl,
                                                 const int* __restrict__ cnt,
                                                 const float* __restrict__ dinv_i,
                                                 float* __restrict__ agg) {
    int node = (blockIdx.x * 256 + threadIdx.x) >> 5;
    int lane = threadIdx.x & 31;
    if (node >= NN) return;
    const float* mr[3] = {m0, m1, m2};
    float ax = 0.f, ay = 0.f, az = 0.f, aw = 0.f;
#pragma unroll
    for (int r = 0; r < NR; r++) {
        const float* m = mr[r];
        int n = cnt[r * NN + node];
        int base = excl[r * NN + node];
        float px = 0.f, py = 0.f, pz = 0.f, pw = 0.f;
        for (int c0 = 0; c0 < n; c0 += 32) {
            int sl = (c0 + lane < n) ? srcidx[base + c0 + lane] : 0;
            int lim = min(32, n - c0);
            int i = 0;
            for (; i + 1 < lim; i += 2) {
                int s0 = __shfl_sync(~0u, sl, i);
                int s1 = __shfl_sync(~0u, sl, i + 1);
                float4 v0 = *(const float4*)(m + (size_t)s0 * DIM + lane * 4);
                float4 v1 = *(const float4*)(m + (size_t)s1 * DIM + lane * 4);
                px += v0.x + v1.x; py += v0.y + v1.y; pz += v0.z + v1.z; pw += v0.w + v1.w;
            }
            if (i < lim) {
                int s0 = __shfl_sync(~0u, sl, i);
                float4 v0 = *(const float4*)(m + (size_t)s0 * DIM + lane * 4);
                px += v0.x; py += v0.y; pz += v0.z; pw += v0.w;
            }
        }
        float sc = dinv_i[r * NN + node];
        ax += sc * px; ay += sc * py; az += sc * pz; aw += sc * pw;
    }
    *(float4*)(agg + (size_t)node * DIM + lane * 4) = make_float4(ax, ay, az, aw);
}

// ---------------- fused 3-relation conv GEMM ----------------
// m_r[row,:] = dinv_o_r[row] * (bnA(A)[row,:] @ W_r), r=0..2; A optionally BN-affine'd per column.
#define G3_TMEM 0
#define G3_MB0 8
#define G3_MB1 16
#define G3_MB2 24
#define G3_BNS 64                  // bnscale[128]
#define G3_BNB 576                 // bnshift[128]
#define G3_A 2048                  // hi 32KB + lo 32KB
#define G3_W 67584                 // two 64KB buffers
#define G3_TOTAL (G3_W + 131072)   // 198656

template <bool BN>
__global__ void __launch_bounds__(256, 1) k_gemm3(const float4* __restrict__ A,
                                                  const uint8_t* __restrict__ Wimg,   // 3 x 64KB
                                                  const float* __restrict__ stats,
                                                  const float* __restrict__ gamma,
                                                  const float* __restrict__ beta,
                                                  const float* __restrict__ dinv_o,   // [NR*NN]
                                                  float* __restrict__ m0,
                                                  float* __restrict__ m1,
                                                  float* __restrict__ m2, int M) {
    extern __shared__ char sm[];
    int tid = threadIdx.x, wid = tid >> 5, lid = tid & 31;
    int row0 = blockIdx.x * 128;

#if HAS_TCGEN05
    uint32_t smb = smem_u32(sm);
    if (tid == 0) {
        MBARRIER_INIT(smb + G3_MB0, 1);
        MBARRIER_INIT(smb + G3_MB1, 1);
        MBARRIER_INIT(smb + G3_MB2, 1);
    }
    if (wid == 0) { TCGEN05_ALLOC(smb + G3_TMEM, 512); }

    float* bns = (float*)(sm + G3_BNS);
    float* bnb = (float*)(sm + G3_BNB);
    if (BN && tid < DIM) {
        float mean = stats[tid] * (1.f / NN);
        float var = stats[DIM + tid] * (1.f / NN) - mean * mean;
        float inv = rsqrtf(var + BN_EPS);
        float sc = gamma[tid] * inv;
        bns[tid] = sc;
        bnb[tid] = beta[tid] - mean * sc;
    }
    __syncthreads();

    // W0 -> buf0, W1 -> buf1 (pre-swizzled images; independent LDGs pipeline)
    {
        const float4* W0 = (const float4*)Wimg;
        const float4* W1 = (const float4*)(Wimg + 65536);
        float4* B0 = (float4*)(sm + G3_W);
        float4* B1 = (float4*)(sm + G3_W + 65536);
#pragma unroll
        for (int i = 0; i < 16; i++) B0[tid + i * 256] = W0[tid + i * 256];
#pragma unroll
        for (int i = 0; i < 16; i++) B1[tid + i * 256] = W1[tid + i * 256];
    }

    // A: 128 rows, batched loads (MLP=8), bf16 hi/lo split, swizzled
#pragma unroll
    for (int g = 0; g < 2; g++) {
        float4 buf[8];
        int idx[8];
#pragma unroll
        for (int b = 0; b < 8; b++) {
            int i = g * 2048 + b * 256 + tid;
            idx[b] = i;
            int grow = row0 + (i >> 5);
            buf[b] = (grow < M) ? A[(size_t)grow * 32 + (i & 31)] : make_float4(0.f, 0.f, 0.f, 0.f);
        }
#pragma unroll
        for (int b = 0; b < 8; b++) {
            int i = idx[b];
            int row = i >> 5, c4 = i & 31;
            float4 v = buf[b];
            if (BN) {
                int c = c4 * 4;
                v.x = v.x * bns[c + 0] + bnb[c + 0];
                v.y = v.y * bns[c + 1] + bnb[c + 1];
                v.z = v.z * bns[c + 2] + bnb[c + 2];
                v.w = v.w * bns[c + 3] + bnb[c + 3];
            }
            split_store(sm + G3_A, sm + G3_A + 32768, tile_off(row, c4 * 4), v);
        }
    }

    FENCE_ASYNC_SHARED();
    __syncthreads();

    uint32_t tmem;
    asm volatile("ld.shared.b32 %0, [%1];" : "=r"(tmem) : "r"(smb + G3_TMEM));

    uint64_t aH = MAKE_SMEM_DESC(smb + G3_A);
    uint64_t aL = MAKE_SMEM_DESC(smb + G3_A + 32768);

    bool issuer = (wid == 0) && elect_one();
    if (issuer) {
#pragma unroll
        for (int r = 0; r < 2; r++) {
            uint64_t bH = MAKE_SMEM_DESC(smb + G3_W + r * 65536);
            uint64_t bL = MAKE_SMEM_DESC(smb + G3_W + r * 65536 + 32768);
            uint64_t ad[3] = {aH, aH, aL};
            uint64_t bd[3] = {bH, bL, bH};
#pragma unroll
            for (int p = 0; p < 3; p++)
#pragma unroll
                for (int s = 0; s < 8; s++) {
                    uint64_t o = (s < 4) ? (uint64_t)(s * 2) : (uint64_t)(1024 + (s - 4) * 2);
                    mma_f16_ss(tmem + r * 128, ad[p] + o, bd[p] + o, MMA_IDESC, !(p == 0 && s == 0));
                }
            TCGEN05_COMMIT(smb + (r == 0 ? G3_MB0 : G3_MB1));
        }
    }

    // wait r0 done -> buf0 free -> stage W2 into buf0 (overlaps r1)
    mbar_wait(smb + G3_MB0, 0);
    {
        const float4* W2 = (const float4*)(Wimg + 131072);
        float4* B0 = (float4*)(sm + G3_W);
#pragma unroll
        for (int i = 0; i < 16; i++) B0[tid + i * 256] = W2[tid + i * 256];
    }
    FENCE_ASYNC_SHARED();
    __syncthreads();

    if (issuer) {
        uint64_t bH = MAKE_SMEM_DESC(smb + G3_W);
        uint64_t bL = MAKE_SMEM_DESC(smb + G3_W + 32768);
        uint64_t ad[3] = {aH, aH, aL};
        uint64_t bd[3] = {bH, bL, bH};
#pragma unroll
        for (int p = 0; p < 3; p++)
#pragma unroll
            for (int s = 0; s < 8; s++) {
                uint64_t o = (s < 4) ? (uint64_t)(s * 2) : (uint64_t)(1024 + (s - 4) * 2);
                mma_f16_ss(tmem + 256, ad[p] + o, bd[p] + o, MMA_IDESC, !(p == 0 && s == 0));
            }
        TCGEN05_COMMIT(smb + G3_MB2);
    }

    mbar_wait(smb + G3_MB1, 0);
    mbar_wait(smb + G3_MB2, 0);
    TCGEN05_FENCE_AFTER();

    // epilogue: rows by subpartition (wid&3), col halves by (wid>>2); 3 relations
    int rb = (wid & 3) * 32 + lid;
    int grow = row0 + rb;
    int chalf = (wid >> 2) * 64;
    float* mouts[3] = {m0, m1, m2};
#pragma unroll
    for (int r = 0; r < NR; r++) {
        float rs = (grow < M) ? dinv_o[r * NN + grow] : 0.f;
        float* op = mouts[r] + (size_t)grow * DIM;
#pragma unroll
        for (int hh = 0; hh < 2; hh++) {
            int cb = chalf + hh * 32;
            uint32_t dr[32];
            TCGEN05_LD_32X32B_X32(dr, tmem + r * 128 + cb);
            TCGEN05_WAIT_LD();
            if (grow < M) {
#pragma unroll
                for (int j = 0; j < 8; j++) {
                    float4 c;
                    c.x = __uint_as_float(dr[4 * j + 0]) * rs;
                    c.y = __uint_as_float(dr[4 * j + 1]) * rs;
                    c.z = __uint_as_float(dr[4 * j + 2]) * rs;
                    c.w = __uint_as_float(dr[4 * j + 3]) * rs;
                    *(float4*)(op + cb + 4 * j) = c;
                }
            }
        }
    }

    __syncthreads();
    if (wid == 0) TCGEN05_DEALLOC(tmem, 512);

#else  // ---------------- fallback: scalar FFMA (non-'a' target) ----------------
    float* Wf = (float*)sm;                 // [128][128]
    float* As = Wf + 16384;                 // staging [16][72]
    float* bns = As + 16 * 72;
    float* bnb = bns + DIM;

    if (BN && tid < DIM) {
        float mean = stats[tid] * (1.f / NN);
        float var = stats[DIM + tid] * (1.f / NN) - mean * mean;
        float inv = rsqrtf(var + BN_EPS);
        float sc = gamma[tid] * inv;
        bns[tid] = sc;
        bnb[tid] = beta[tid] - mean * sc;
    }
    __syncthreads();

    float* mouts[3] = {m0, m1, m2};
    for (int r = 0; r < NR; r++) {
        for (int i = tid; i < 16384; i += 256) {
            int k = i >> 7, n = i & 127;
            uint32_t off = tile_off(n, k);
            const uint8_t* Wr = Wimg + (size_t)r * 65536;
            Wf[i] = __bfloat162float(*(const __nv_bfloat16*)(Wr + off)) +
                    __bfloat162float(*(const __nv_bfloat16*)(Wr + 32768 + off));
        }
        __syncthreads();

        int rbase = (tid >> 5) * 8;
        int cbase = (tid & 31) * 4;
        int arow = tid >> 2;
        int ak = (tid & 3) * 4;

        for (int half = 0; half < 2; half++) {
            int r0r = row0 + half * 64;
            int grow = r0r + arow;
            bool rowok = grow < M;
            const float4* Ar = A + (size_t)grow * 32;

            float acc[8][4];
#pragma unroll
            for (int i = 0; i < 8; i++)
#pragma unroll
                for (int j = 0; j < 4; j++) acc[i][j] = 0.f;

            for (int kt = 0; kt < 8; ++kt) {
                float4 av = rowok ? Ar[kt * 4 + (tid & 3)] : make_float4(0.f, 0.f, 0.f, 0.f);
                if (BN) {
                    av.x = av.x * bns[ak + kt * 16 - ak + ak] ; // placeholder avoided below
                }
                // apply BN per column (column = kt*16 + ak + j is wrong mapping; compute directly)
                if (BN) {
                    int c = kt * 16 + ak;
                    av.x = av.x * bns[c + 0] + bnb[c + 0];
                    av.y = av.y * bns[c + 1] + bnb[c + 1];
                    av.z = av.z * bns[c + 2] + bnb[c + 2];
                    av.w = av.w * bns[c + 3] + bnb[c + 3];
                }
                As[(ak + 0) * 72 + arow] = av.x;
                As[(ak + 1) * 72 + arow] = av.y;
                As[(ak + 2) * 72 + arow] = av.z;
                As[(ak + 3) * 72 + arow] = av.w;
                __syncthreads();
#pragma unroll
                for (int kk = 0; kk < 16; ++kk) {
                    float4 b4 = *(float4*)&Wf[(kt * 16 + kk) * 128 + cbase];
                    float4 a0 = *(float4*)&As[kk * 72 + rbase];
                    float4 a1 = *(float4*)&As[kk * 72 + rbase + 4];
                    float a[8] = {a0.x, a0.y, a0.z, a0.w, a1.x, a1.y, a1.z, a1.w};
#pragma unroll
                    for (int i = 0; i < 8; i++) {
                        acc[i][0] += a[i] * b4.x;
                        acc[i][1] += a[i] * b4.y;
                        acc[i][2] += a[i] * b4.z;
                        acc[i][3] += a[i] * b4.w;
                    }
                }
                __syncthreads();
            }
#pragma unroll
            for (int i = 0; i < 8; i++) {
                int rr = r0r + rbase + i;
                if (rr < M) {
                    float rs = dinv_o[r * NN + rr];
                    float4 c;
                    c.x = acc[i][0] * rs; c.y = acc[i][1] * rs;
                    c.z = acc[i][2] * rs; c.w = acc[i][3] * rs;
                    *(float4*)(mouts[r] + (size_t)rr * DIM + cbase) = c;
                }
            }
        }
        __syncthreads();
    }
#endif
}

// ---------------- FC GEMM (M=256 per CTA): C = relu(A @ W + bias) ----------------
#define SM_TMEM 0
#define SM_MBAR 8
#define SM_A 1024
#define SM_W (SM_A + 131072)
#define SM_TOTAL (SM_W + 65536)

__global__ void __launch_bounds__(256, 1) k_gemm_fc(const float4* __restrict__ A,
                                                    const uint8_t* __restrict__ Wimg,
                                                    const float* __restrict__ bias,
                                                    float* __restrict__ C, int M) {
    extern __shared__ char sm[];
    int tid = threadIdx.x, wid = tid >> 5, lid = tid & 31;
    int row0 = blockIdx.x * 256;

#if HAS_TCGEN05
    uint32_t smb = smem_u32(sm);
    if (tid == 0) MBARRIER_INIT(smb + SM_MBAR, 1);
    if (wid == 0) { TCGEN05_ALLOC(smb + SM_TMEM, 256); }
    __syncthreads();

    {
        const float4* Wv = (const float4*)Wimg;
        float4* Bv = (float4*)(sm + SM_W);
#pragma unroll
        for (int i = 0; i < 16; i++) Bv[tid + i * 256] = Wv[tid + i * 256];
    }

#pragma unroll
    for (int g = 0; g < 4; g++) {
        float4 buf[8];
        int idx[8];
#pragma unroll
        for (int b = 0; b < 8; b++) {
            int i = g * 2048 + b * 256 + tid;
            idx[b] = i;
            int grow = row0 + (i >> 5);
            buf[b] = (grow < M) ? A[(size_t)grow * 32 + (i & 31)] : make_float4(0.f, 0.f, 0.f, 0.f);
        }
#pragma unroll
        for (int b = 0; b < 8; b++) {
            int i = idx[b];
            int row = i >> 5, c4 = i & 31;
            int t = row >> 7, lrow = row & 127;
            split_store(sm + SM_A + t * 65536, sm + SM_A + t * 65536 + 32768,
                        tile_off(lrow, c4 * 4), buf[b]);
        }
    }

    FENCE_ASYNC_SHARED();
    __syncthreads();

    uint32_t tmem;
    asm volatile("ld.shared.b32 %0, [%1];" : "=r"(tmem) : "r"(smb + SM_TMEM));

    if (wid == 0 && elect_one()) {
        uint64_t bH = MAKE_SMEM_DESC(smb + SM_W);
        uint64_t bL = MAKE_SMEM_DESC(smb + SM_W + 32768);
#pragma unroll
        for (int t = 0; t < 2; t++) {
            uint64_t aH = MAKE_SMEM_DESC(smb + SM_A + t * 65536);
            uint64_t aL = MAKE_SMEM_DESC(smb + SM_A + t * 65536 + 32768);
            uint64_t ad[3] = {aH, aH, aL};
            uint64_t bd[3] = {bH, bL, bH};
#pragma unroll
            for (int p = 0; p < 3; p++)
#pragma unroll
                for (int s = 0; s < 8; s++) {
                    uint64_t o = (s < 4) ? (uint64_t)(s * 2) : (uint64_t)(1024 + (s - 4) * 2);
                    mma_f16_ss(tmem + t * 128, ad[p] + o, bd[p] + o, MMA_IDESC, !(p == 0 && s == 0));
                }
        }
        TCGEN05_COMMIT(smb + SM_MBAR);
    }

    mbar_wait(smb + SM_MBAR, 0);
    TCGEN05_FENCE_AFTER();

#pragma unroll
    for (int t = 0; t < 2; t++) {
        int rb = t * 128 + (wid & 3) * 32 + lid;
        int grow = row0 + rb;
        int chalf = (wid >> 2) * 64;
#pragma unroll
        for (int hh = 0; hh < 2; hh++) {
            int cb = chalf + hh * 32;
            uint32_t dr[32];
            TCGEN05_LD_32X32B_X32(dr, tmem + t * 128 + cb);
            TCGEN05_WAIT_LD();
            if (grow < M) {
                float* op = C + (size_t)grow * DIM + cb;
#pragma unroll
                for (int j = 0; j < 8; j++) {
                    float4 bv = *(const float4*)(bias + cb + 4 * j);
                    float4 c;
                    c.x = fmaxf(__uint_as_float(dr[4 * j + 0]) + bv.x, 0.f);
                    c.y = fmaxf(__uint_as_float(dr[4 * j + 1]) + bv.y, 0.f);
                    c.z = fmaxf(__uint_as_float(dr[4 * j + 2]) + bv.z, 0.f);
                    c.w = fmaxf(__uint_as_float(dr[4 * j + 3]) + bv.w, 0.f);
                    *(float4*)(op + 4 * j) = c;
                }
            }
        }
    }

    __syncthreads();
    if (wid == 0) TCGEN05_DEALLOC(tmem, 256);

#else  // fallback
    float* Wf = (float*)sm;
    float* As = Wf + 16384;

    for (int i = tid; i < 16384; i += 256) {
        int k = i >> 7, n = i & 127;
        uint32_t off = tile_off(n, k);
        Wf[i] = __bfloat162float(*(const __nv_bfloat16*)(Wimg + off)) +
                __bfloat162float(*(const __nv_bfloat16*)(Wimg + 32768 + off));
    }
    __syncthreads();

    int rbase = (tid >> 5) * 8;
    int cbase = (tid & 31) * 4;
    int arow = tid >> 2;
    int ak = (tid & 3) * 4;

    for (int half = 0; half < 4; half++) {
        int r0 = row0 + half * 64;
        int grow = r0 + arow;
        bool rowok = grow < M;
        const float4* Ar = A + (size_t)grow * 32;

        float acc[8][4];
#pragma unroll
        for (int i = 0; i < 8; i++)
#pragma unroll
            for (int j = 0; j < 4; j++) acc[i][j] = 0.f;

        for (int kt = 0; kt < 8; ++kt) {
            float4 av = rowok ? Ar[kt * 4 + (tid & 3)] : make_float4(0.f, 0.f, 0.f, 0.f);
            As[(ak + 0) * 72 + arow] = av.x;
            As[(ak + 1) * 72 + arow] = av.y;
            As[(ak + 2) * 72 + arow] = av.z;
            As[(ak + 3) * 72 + arow] = av.w;
            __syncthreads();
#pragma unroll
            for (int kk = 0; kk < 16; ++kk) {
                float4 b4 = *(float4*)&Wf[(kt * 16 + kk) * 128 + cbase];
                float4 a0 = *(float4*)&As[kk * 72 + rbase];
                float4 a1 = *(float4*)&As[kk * 72 + rbase + 4];
                float a[8] = {a0.x, a0.y, a0.z, a0.w, a1.x, a1.y, a1.z, a1.w};
#pragma unroll
                for (int i = 0; i < 8; i++) {
                    acc[i][0] += a[i] * b4.x;
                    acc[i][1] += a[i] * b4.y;
                    acc[i][2] += a[i] * b4.z;
                    acc[i][3] += a[i] * b4.w;
                }
            }
            __syncthreads();
        }

        float4 bv = *(const float4*)(bias + cbase);
#pragma unroll
        for (int i = 0; i < 8; i++) {
            int r = r0 + rbase + i;
            if (r < M) {
                float4 c;
                c.x = fmaxf(acc[i][0] + bv.x, 0.f);
                c.y = fmaxf(acc[i][1] + bv.y, 0.f);
                c.z = fmaxf(acc[i][2] + bv.z, 0.f);
                c.w = fmaxf(acc[i][3] + bv.w, 0.f);
                *(float4*)(C + (size_t)r * DIM + cbase) = c;
            }
        }
    }
#endif
}

// ---------------- BatchNorm ----------------
__global__ void __launch_bounds__(128) k_bnstats(const float* __restrict__ h, float* __restrict__ stats) {
    int c = threadIdx.x;
    float s = 0.f, s2 = 0.f;
    for (int r = blockIdx.x; r < NN; r += gridDim.x) {
        float v = h[(size_t)r * DIM + c];
        s += v;
        s2 += v * v;
    }
    atomicAdd(&stats[c], s);
    atomicAdd(&stats[DIM + c], s2);
}
__global__ void __launch_bounds__(256) k_bnnorm(const float* __restrict__ h,
                                                const float* __restrict__ stats,
                                                const float* __restrict__ gamma,
                                                const float* __restrict__ beta,
                                                float* __restrict__ out) {
    int i = blockIdx.x * 256 + threadIdx.x;
    if (i >= NN * DIM / 4) return;
    int c = (i & 31) * 4;
    float4 v = *(const float4*)(h + (size_t)i * 4);
    float vin[4] = {v.x, v.y, v.z, v.w};
    float o[4];
#pragma unroll
    for (int j = 0; j < 4; j++) {
        float mean = stats[c + j] * (1.f / NN);
        float var = stats[DIM + c + j] * (1.f / NN) - mean * mean;
        float inv = rsqrtf(var + BN_EPS);
        o[j] = (vin[j] - mean) * inv * gamma[c + j] + beta[c + j];
    }
    *(float4*)(out + (size_t)i * 4) = make_float4(o[0], o[1], o[2], o[3]);
}

// ---------------- launch ----------------
extern "C" void kernel_launch(void* const* d_in, const int* in_sizes, int n_in,
                              void* d_out, int out_size) {
    const float* x      = (const float*)d_in[0];
    const int*   edges  = (const int*)d_in[1];
    const float* conv_W = (const float*)d_in[2];
    const float* conv_b = (const float*)d_in[3];
    const float* fc_W   = (const float*)d_in[4];
    const float* fc_b   = (const float*)d_in[5];
    const float* gamma  = (const float*)d_in[6];
    const float* beta   = (const float*)d_in[7];
    float* out = (float*)d_out;

    float *h, *m0, *m1, *m2, *agg, *dinv_o, *dinv_i, *stats, *fceff;
    int *cnt_in, *cnt_out, *cursor, *excl, *bsum, *srcidx;
    uint8_t* wbf;
    cudaGetSymbolAddress((void**)&h, g_h);
    cudaGetSymbolAddress((void**)&m0, g_m0);
    cudaGetSymbolAddress((void**)&m1, g_m1);
    cudaGetSymbolAddress((void**)&m2, g_m2);
    cudaGetSymbolAddress((void**)&agg, g_agg);
    cudaGetSymbolAddress((void**)&dinv_o, g_dinv_o);
    cudaGetSymbolAddress((void**)&dinv_i, g_dinv_i);
    cudaGetSymbolAddress((void**)&cnt_in, g_cnt_in);
    cudaGetSymbolAddress((void**)&cnt_out, g_cnt_out);
    cudaGetSymbolAddress((void**)&cursor, g_cursor);
    cudaGetSymbolAddress((void**)&excl, g_excl);
    cudaGetSymbolAddress((void**)&bsum, g_bsum);
    cudaGetSymbolAddress((void**)&srcidx, g_srcidx);
    cudaGetSymbolAddress((void**)&stats, g_stats);
    cudaGetSymbolAddress((void**)&wbf, g_Wbf);
    cudaGetSymbolAddress((void**)&fceff, g_fceff);

    cudaFuncSetAttribute(k_gemm3<false>, cudaFuncAttributeMaxDynamicSharedMemorySize, G3_TOTAL);
    cudaFuncSetAttribute(k_gemm3<true>, cudaFuncAttributeMaxDynamicSharedMemorySize, G3_TOTAL);
    cudaFuncSetAttribute(k_gemm_fc, cudaFuncAttributeMaxDynamicSharedMemorySize, SM_TOTAL);

    const int nh4 = NN * DIM / 4;
    const int NSC = NR * NN;
    const int NB1 = (NSC + 1023) / 1024;

    // ---- prep ----
    k_wprep<<<(12 * 16384 + 255) / 256, 256>>>(conv_W, fc_W, wbf);
    k_bprep<<<NL, 128>>>(conv_b, fc_W, fc_b, fceff);

    k_zeroi<<<(NSC + 255) / 256, 256>>>(cnt_in, NSC);
    k_zeroi<<<(NSC + 255) / 256, 256>>>(cnt_out, NSC);
    k_zeroi<<<(NSC + 255) / 256, 256>>>(cursor, NSC);
    k_cnt<<<(NR * NE + 255) / 256, 256>>>(edges, cnt_out, cnt_in);
    k_dinv<<<(NSC + 255) / 256, 256>>>(cnt_out, cnt_in, dinv_o, dinv_i);

    k_scan1<<<NB1, 1024>>>(cnt_in, excl, bsum, NSC);
    k_scan2<<<1, 512>>>(bsum, NB1);
    k_scan3<<<NB1, 1024>>>(excl, bsum, NSC);
    k_place<<<(NR * NE + 255) / 256, 256>>>(edges, excl, cursor, srcidx);

    const int GGRID = (NN * 32 + 255) / 256;
    const int G3GRID = (NN + 127) / 128;     // 782
    const int FCGRID = (NN + 255) / 256;     // 391

    for (int l = 0; l < NL; ++l) {
        // fused conv GEMMs (BN of previous layer folded into A-load for l>0)
        if (l == 0)
            k_gemm3<false><<<G3GRID, 256, G3_TOTAL>>>(
                (const float4*)x, wbf + (size_t)(l * NR) * 65536,
                nullptr, nullptr, nullptr, dinv_o, m0, m1, m2, NN);
        else
            k_gemm3<true><<<G3GRID, 256, G3_TOTAL>>>(
                (const float4*)h, wbf + (size_t)(l * NR) * 65536,
                stats, gamma + (size_t)(l - 1) * DIM, beta + (size_t)(l - 1) * DIM,
                dinv_o, m0, m1, m2, NN);
        // fused 3-relation gather
        k_gather3<<<GGRID, 256>>>(m0, m1, m2, srcidx, excl, cnt_in, dinv_i, agg);
        // FC + ReLU
        k_gemm_fc<<<FCGRID, 256, SM_TOTAL>>>((const float4*)agg,
                                             wbf + (size_t)(9 + l) * 65536,
                                             fceff + (size_t)l * DIM, h, NN);
        // BN stats on h (affine applied in next layer's A-load, or k_bnnorm for final)
        k_zero<<<1, 256>>>((float4*)stats, 2 * DIM / 4);
        k_bnstats<<<1024, 128>>>(h, stats);
    }
    k_bnnorm<<<(nh4 + 255) / 256, 256>>>(h, stats,
                                         gamma + (size_t)(NL - 1) * DIM,
                                         beta + (size_t)(NL - 1) * DIM, out);
}